// round 1
// baseline (speedup 1.0000x reference)
#include <cuda_runtime.h>
#include <math.h>

#define BATCH   4
#define SEQLEN  4096
#define DIM     512
#define DINNER  1024
#define DSTATE  16
#define DCONV   4
#define M_TOK   (BATCH*SEQLEN)   // 16384

// ---------------- scratch (device globals; no allocation allowed) -----------
__device__ float g_xr   [(size_t)M_TOK * 2 * DINNER];  // x_and_res  (xi | res)
__device__ float g_xa   [(size_t)M_TOK * DINNER];      // silu(conv(xi)+b)
__device__ float g_wcat [2 * DSTATE * DINNER];         // [W_dt rows 0..15 ; W_x rows 16..31]
__device__ float g_dtb  [(size_t)M_TOK * 2 * DSTATE];  // raw dt | B_proj
__device__ float g_u    [M_TOK];
__device__ float g_adisc[(size_t)M_TOK * DSTATE];
__device__ float g_bu   [(size_t)M_TOK * DSTATE];
__device__ float g_y    [(size_t)M_TOK * DSTATE];
__device__ float g_yfull[(size_t)M_TOK * DINNER];

// ---------------- generic NT GEMM: C[M,N] = A[M,K] * B[N,K]^T ---------------
// Both A and B are K-major (row-major with K contiguous). No bounds checks:
// all shapes here are exact multiples of the tiles.
template<int BM, int BN, int BK, int TM, int TN>
__global__ __launch_bounds__((BM/TM)*(BN/TN))
void gemm_nt(const float* __restrict__ A, const float* __restrict__ B,
             float* __restrict__ C, int M, int N, int K)
{
    constexpr int TX = BN / TN;
    constexpr int TY = BM / TM;
    constexpr int NT = TX * TY;

    __shared__ float As[BK][BM];
    __shared__ float Bs[BK][BN];

    const int tid = threadIdx.x;
    const int tx  = tid % TX;
    const int ty  = tid / TX;
    const int m0  = blockIdx.y * BM;
    const int n0  = blockIdx.x * BN;

    float acc[TM][TN];
#pragma unroll
    for (int i = 0; i < TM; i++)
#pragma unroll
        for (int j = 0; j < TN; j++) acc[i][j] = 0.f;

    for (int k0 = 0; k0 < K; k0 += BK) {
        constexpr int A4 = BM * BK / 4;
#pragma unroll
        for (int i = tid; i < A4; i += NT) {
            int r  = i / (BK / 4);
            int c4 = i % (BK / 4);
            float4 v = *reinterpret_cast<const float4*>(
                &A[(size_t)(m0 + r) * K + k0 + c4 * 4]);
            As[c4*4+0][r] = v.x; As[c4*4+1][r] = v.y;
            As[c4*4+2][r] = v.z; As[c4*4+3][r] = v.w;
        }
        constexpr int B4 = BN * BK / 4;
#pragma unroll
        for (int i = tid; i < B4; i += NT) {
            int r  = i / (BK / 4);
            int c4 = i % (BK / 4);
            float4 v = *reinterpret_cast<const float4*>(
                &B[(size_t)(n0 + r) * K + k0 + c4 * 4]);
            Bs[c4*4+0][r] = v.x; Bs[c4*4+1][r] = v.y;
            Bs[c4*4+2][r] = v.z; Bs[c4*4+3][r] = v.w;
        }
        __syncthreads();

#pragma unroll
        for (int k = 0; k < BK; k++) {
            float ar[TM], br[TN];
#pragma unroll
            for (int i = 0; i < TM; i++) ar[i] = As[k][ty * TM + i];
#pragma unroll
            for (int j = 0; j < TN; j++) br[j] = Bs[k][tx * TN + j];
#pragma unroll
            for (int i = 0; i < TM; i++)
#pragma unroll
                for (int j = 0; j < TN; j++)
                    acc[i][j] = fmaf(ar[i], br[j], acc[i][j]);
        }
        __syncthreads();
    }

#pragma unroll
    for (int i = 0; i < TM; i++) {
        float* crow = &C[(size_t)(m0 + ty * TM + i) * N + n0 + tx * TN];
#pragma unroll
        for (int j = 0; j < TN; j++) crow[j] = acc[i][j];
    }
}

// ---------------- build concatenated [W_dt ; W_x rows 16..31] ---------------
__global__ void wcat_kernel(const float* __restrict__ Wx,
                            const float* __restrict__ Wdt)
{
    int idx = blockIdx.x * blockDim.x + threadIdx.x;   // 32*1024
    int row = idx >> 10;
    int col = idx & 1023;
    // row < 16 -> W_dt[row]; row >= 16 -> W_x[row] (B_proj uses W_x rows 16..31)
    g_wcat[idx] = (row < DSTATE) ? Wdt[row * DINNER + col]
                                 : Wx [row * DINNER + col];
}

// ---------------- depthwise causal conv(4) + bias + SiLU --------------------
__global__ void conv_silu_kernel(const float* __restrict__ cw,
                                 const float* __restrict__ cb)
{
    int idx = blockIdx.x * blockDim.x + threadIdx.x;   // M_TOK * DINNER/4
    int c4  = idx & (DINNER/4 - 1);
    int m   = idx >> 8;
    int c   = c4 * 4;
    int l   = m & (SEQLEN - 1);

    float w[4][4];
#pragma unroll
    for (int j = 0; j < 4; j++)
        *reinterpret_cast<float4*>(w[j]) =
            *reinterpret_cast<const float4*>(cw + (size_t)(c + j) * DCONV);

    float4 b = *reinterpret_cast<const float4*>(cb + c);
    float a0 = b.x, a1 = b.y, a2 = b.z, a3 = b.w;

#pragma unroll
    for (int t = 0; t < DCONV; t++) {
        int ls = l - (DCONV - 1) + t;
        if (ls >= 0) {
            float4 xv = *reinterpret_cast<const float4*>(
                g_xr + (size_t)(m - (DCONV - 1) + t) * (2 * DINNER) + c);
            a0 = fmaf(w[0][t], xv.x, a0);
            a1 = fmaf(w[1][t], xv.y, a1);
            a2 = fmaf(w[2][t], xv.z, a2);
            a3 = fmaf(w[3][t], xv.w, a3);
        }
    }
    float4 o;
    o.x = a0 / (1.f + expf(-a0));
    o.y = a1 / (1.f + expf(-a1));
    o.z = a2 / (1.f + expf(-a2));
    o.w = a3 / (1.f + expf(-a3));
    *reinterpret_cast<float4*>(g_xa + (size_t)m * DINNER + c) = o;
}

// ---------------- u[m] = mean(xa[m, 0:64]) ----------------------------------
__global__ void u_kernel()
{
    int gw   = (blockIdx.x * blockDim.x + threadIdx.x) >> 5;  // one warp per token
    int lane = threadIdx.x & 31;
    if (gw >= M_TOK) return;
    const float* xa = g_xa + (size_t)gw * DINNER;
    float v = xa[lane] + xa[lane + 32];
#pragma unroll
    for (int o = 16; o; o >>= 1) v += __shfl_down_sync(0xffffffffu, v, o);
    if (lane == 0) g_u[gw] = v * (1.f / 64.f);
}

// ---------------- dt = softplus(raw+b), A_disc, Bu --------------------------
__global__ void dtbu_kernel(const float* __restrict__ bdt,
                            const float* __restrict__ Alog)
{
    int idx = blockIdx.x * blockDim.x + threadIdx.x;   // M_TOK * DSTATE
    int m = idx >> 4;
    int n = idx & (DSTATE - 1);
    float raw = g_dtb[(size_t)m * 2 * DSTATE + n] + bdt[n];
    float dt  = raw > 20.f ? raw : log1pf(expf(raw));
    float bp  = g_dtb[(size_t)m * 2 * DSTATE + DSTATE + n];
    float A   = -expf(Alog[n]);
    g_adisc[idx] = expf(A * dt);
    g_bu[idx]    = dt * bp * g_u[m];
}

// ---------------- sequential scan: 64 independent chains --------------------
__global__ void scan_kernel()
{
    int t = blockIdx.x * blockDim.x + threadIdx.x;
    if (t >= BATCH * DSTATE) return;
    int b = t / DSTATE;
    int n = t % DSTATE;
    const float* ad = g_adisc + (size_t)b * SEQLEN * DSTATE + n;
    const float* bu = g_bu    + (size_t)b * SEQLEN * DSTATE + n;
    float*       y  = g_y     + (size_t)b * SEQLEN * DSTATE + n;
    float s = 0.f;
#pragma unroll 8
    for (int l = 0; l < SEQLEN; l++) {
        s = fmaf(s, ad[(size_t)l * DSTATE], bu[(size_t)l * DSTATE]);
        y[(size_t)l * DSTATE] = s;
    }
}

// ---------------- y_full = (repeat(y) + xa*D) * silu(res) -------------------
__global__ void elt_kernel(const float* __restrict__ Dp)
{
    int idx = blockIdx.x * blockDim.x + threadIdx.x;   // M_TOK * DINNER/4
    int c4  = idx & (DINNER/4 - 1);
    int m   = idx >> 8;
    int c   = c4 * 4;
    float yv   = g_y[(size_t)m * DSTATE + (c >> 6)];   // d_rep = 64
    float4 xa  = *reinterpret_cast<const float4*>(g_xa + (size_t)m * DINNER + c);
    float4 D   = *reinterpret_cast<const float4*>(Dp + c);
    float4 r   = *reinterpret_cast<const float4*>(g_xr + (size_t)m * 2 * DINNER + DINNER + c);
    float4 o;
    o.x = (yv + xa.x * D.x) * (r.x / (1.f + expf(-r.x)));
    o.y = (yv + xa.y * D.y) * (r.y / (1.f + expf(-r.y)));
    o.z = (yv + xa.z * D.z) * (r.z / (1.f + expf(-r.z)));
    o.w = (yv + xa.w * D.w) * (r.w / (1.f + expf(-r.w)));
    *reinterpret_cast<float4*>(g_yfull + (size_t)m * DINNER + c) = o;
}

// ---------------------------------------------------------------------------
extern "C" void kernel_launch(void* const* d_in, const int* in_sizes, int n_in,
                              void* d_out, int out_size)
{
    const float* x      = (const float*)d_in[0];   // [4,4096,512]
    const float* W_in   = (const float*)d_in[1];   // [2048,512]
    const float* conv_w = (const float*)d_in[2];   // [1024,1,4]
    const float* conv_b = (const float*)d_in[3];   // [1024]
    const float* W_x    = (const float*)d_in[4];   // [32,1024]
    const float* W_dt   = (const float*)d_in[5];   // [16,1024]
    const float* b_dt   = (const float*)d_in[6];   // [16]
    const float* A_log  = (const float*)d_in[7];   // [1,16]
    const float* D_par  = (const float*)d_in[8];   // [1024]
    const float* W_out  = (const float*)d_in[9];   // [512,1024]
    float* out = (float*)d_out;                    // [4,4096,512]

    float* xr;    cudaGetSymbolAddress((void**)&xr,    g_xr);
    float* xa;    cudaGetSymbolAddress((void**)&xa,    g_xa);
    float* wcat;  cudaGetSymbolAddress((void**)&wcat,  g_wcat);
    float* dtb;   cudaGetSymbolAddress((void**)&dtb,   g_dtb);
    float* yfull; cudaGetSymbolAddress((void**)&yfull, g_yfull);

    // 0. concat weight rows for the small GEMM
    wcat_kernel<<<(2*DSTATE*DINNER)/256, 256>>>(W_x, W_dt);

    // 1. x_and_res = x @ W_in^T     [16384 x 2048 x 512]
    gemm_nt<128,64,16,8,4><<<dim3(2*DINNER/64, M_TOK/128), 256>>>(
        x, W_in, xr, M_TOK, 2*DINNER, DIM);

    // 2. xa = silu(causal_conv(xi) + b)
    conv_silu_kernel<<<(M_TOK*(DINNER/4))/256, 256>>>(conv_w, conv_b);

    // 3. u = mean(xa[:, :64])
    u_kernel<<<(M_TOK*32)/256, 256>>>();

    // 4. [dt_raw | B_proj] = xa @ wcat^T   [16384 x 32 x 1024]
    gemm_nt<64,32,16,4,2><<<dim3(1, M_TOK/64), 256>>>(
        xa, wcat, dtb, M_TOK, 2*DSTATE, DINNER);

    // 5. dt / A_disc / Bu
    dtbu_kernel<<<(M_TOK*DSTATE)/256, 256>>>(b_dt, A_log);

    // 6. sequential scan (64 chains)
    scan_kernel<<<1, BATCH*DSTATE>>>();

    // 7. gate + skip
    elt_kernel<<<(M_TOK*(DINNER/4))/256, 256>>>(D_par);

    // 8. out = y_full @ W_out^T     [16384 x 512 x 1024]
    gemm_nt<128,64,16,8,4><<<dim3(DIM/64, M_TOK/128), 256>>>(
        yfull, W_out, out, M_TOK, DIM, DINNER);
}

// round 4
// speedup vs baseline: 2.7189x; 2.7189x over previous
#include <cuda_runtime.h>
#include <cuda_bf16.h>
#include <math.h>
#include <stdint.h>

#define BATCH   4
#define SEQLEN  4096
#define DIM     512
#define DINNER  1024
#define DSTATE  16
#define DCONV   4
#define M_TOK   (BATCH*SEQLEN)   // 16384

// ======================= PTX helpers (sm_80 baseline) ========================
__device__ __forceinline__ uint32_t smem_to_u32(const void* p) {
    uint32_t a;
    asm("{ .reg .u64 t; cvta.to.shared.u64 t, %1; cvt.u32.u64 %0, t; }"
        : "=r"(a) : "l"(p));
    return a;
}
#define CP_ASYNC16(saddr, gptr) \
    asm volatile("cp.async.cg.shared.global [%0], [%1], 16;" \
        :: "r"(saddr), "l"(gptr))
#define CP_COMMIT() asm volatile("cp.async.commit_group;" ::: "memory")
#define CP_WAIT1()  asm volatile("cp.async.wait_group 1;" ::: "memory")
#define CP_WAIT0()  asm volatile("cp.async.wait_group 0;" ::: "memory")

#define LDSM_X4(r, addr) \
    asm volatile("ldmatrix.sync.aligned.m8n8.x4.shared.b16 {%0,%1,%2,%3}, [%4];" \
        : "=r"((r)[0]), "=r"((r)[1]), "=r"((r)[2]), "=r"((r)[3]) : "r"(addr))

#define MMA_BF16(d, a, b0, b1) \
    asm volatile("mma.sync.aligned.m16n8k16.row.col.f32.bf16.bf16.f32 " \
        "{%0,%1,%2,%3}, {%4,%5,%6,%7}, {%8,%9}, {%0,%1,%2,%3};" \
        : "+f"((d)[0]), "+f"((d)[1]), "+f"((d)[2]), "+f"((d)[3]) \
        : "r"((a)[0]), "r"((a)[1]), "r"((a)[2]), "r"((a)[3]), "r"(b0), "r"(b1))

// ======================= scratch =============================================
__device__ __align__(256) float g_xr  [(size_t)M_TOK * 2 * DINNER];
__device__ __align__(256) float g_xa  [(size_t)M_TOK * DINNER];
__device__ __align__(256) float g_wcat[2 * DSTATE * DINNER];
__device__ __align__(256) float g_dtb [(size_t)M_TOK * 2 * DSTATE];
__device__ __align__(256) float g_u   [M_TOK];
__device__ __align__(256) float g_adisc[(size_t)M_TOK * DSTATE];
__device__ __align__(256) float g_bu  [(size_t)M_TOK * DSTATE];
__device__ __align__(256) float g_y   [(size_t)M_TOK * DSTATE];
// bf16 split operands: A-side = [hi | lo | hi], B-side = [hi | hi | lo]
__device__ __align__(256) __nv_bfloat16 g_xb [(size_t)M_TOK * 3 * DIM];
__device__ __align__(256) __nv_bfloat16 g_wib[(size_t)2*DINNER * 3 * DIM];
__device__ __align__(256) __nv_bfloat16 g_yb [(size_t)M_TOK * 3 * DINNER];
__device__ __align__(256) __nv_bfloat16 g_wob[(size_t)DIM * 3 * DINNER];
// scan chunk summaries
#define SCHUNK  128
#define NCHUNK  (SEQLEN / SCHUNK)   // 32
__device__ float g_cA   [BATCH * DSTATE * NCHUNK];
__device__ float g_cV   [BATCH * DSTATE * NCHUNK];
__device__ float g_carry[BATCH * DSTATE * NCHUNK];

// ======================= HMMA GEMM ===========================================
// C[M,N] = A''[M,Kpp] * B''[N,Kpp]^T, bf16 K-major inputs, fp32 out.
// Block tile 128x128, K-chunk 64 bf16 (128B/row), 128 threads (4 warps, 2x2),
// cp.async double buffer, ldmatrix + mma.sync.m16n8k16.
// smem: 4 tiles of 128 rows x 144B (72 bf16) = 4*18432 = 73728 B
#define LG_ROWB   144                      // bytes per smem row (pad vs 128)
#define LG_TILE_B (128 * LG_ROWB)          // 18432 bytes per tile
#define GH_SMEM   (4 * LG_TILE_B)          // 73728

__global__ __launch_bounds__(128)
void gemm_hmma(const __nv_bfloat16* __restrict__ A, const __nv_bfloat16* __restrict__ B,
               float* __restrict__ C, int Nglob, int Kpp)
{
    extern __shared__ char smem[];
    const uint32_t sb = smem_to_u32(smem);
    const int tid  = threadIdx.x;
    const int wid  = tid >> 5;
    const int lane = tid & 31;
    const int m0 = blockIdx.y * 128;
    const int n0 = blockIdx.x * 128;
    const int nch = Kpp / 64;

    // warp -> 64x64 sub-tile
    const int wm = (wid >> 1) * 64;
    const int wn = (wid &  1) * 64;

    // smem byte offsets: [A0 | B0 | A1 | B1]
    const uint32_t offA[2] = { 0u,              2u * LG_TILE_B };
    const uint32_t offB[2] = { (uint32_t)LG_TILE_B, 3u * LG_TILE_B };

    float acc[4][8][4];
#pragma unroll
    for (int i = 0; i < 4; i++)
#pragma unroll
        for (int j = 0; j < 8; j++)
#pragma unroll
            for (int k = 0; k < 4; k++) acc[i][j][k] = 0.f;

    // async-copy one K-chunk (128 rows x 128B) of A and B into buffer b
    auto issue = [&](int c, int b) {
        const __nv_bfloat16* Ag = A + (size_t)m0 * Kpp + (size_t)c * 64;
        const __nv_bfloat16* Bg = B + (size_t)n0 * Kpp + (size_t)c * 64;
        const uint32_t sa  = sb + offA[b];
        const uint32_t sbm = sb + offB[b];
#pragma unroll
        for (int i = 0; i < 8; i++) {
            int idx = tid + i * 128;              // 0..1023
            int row = idx >> 3, cc = idx & 7;     // 8 x 16B per 128B row
            CP_ASYNC16(sa  + (uint32_t)(row * LG_ROWB + cc * 16),
                       Ag + (size_t)row * Kpp + cc * 8);
            CP_ASYNC16(sbm + (uint32_t)(row * LG_ROWB + cc * 16),
                       Bg + (size_t)row * Kpp + cc * 8);
        }
        CP_COMMIT();
    };

    issue(0, 0);
    for (int c = 0; c < nch; c++) {
        const int buf = c & 1;
        if (c + 1 < nch) { issue(c + 1, buf ^ 1); CP_WAIT1(); }
        else             { CP_WAIT0(); }
        __syncthreads();

        const uint32_t aBase = sb + offA[buf];
        const uint32_t bBase = sb + offB[buf];
        const int lrow = lane & 15;
        const int lcol = (lane >> 4) * 16;        // byte offset of k-half
#pragma unroll
        for (int ks = 0; ks < 4; ks++) {          // 4 x k16 per 64-chunk
            uint32_t af[4][4], bfr[4][4];
#pragma unroll
            for (int mt = 0; mt < 4; mt++)
                LDSM_X4(af[mt], aBase + (uint32_t)((wm + mt*16 + lrow) * LG_ROWB + ks*32 + lcol));
#pragma unroll
            for (int ng = 0; ng < 4; ng++)
                LDSM_X4(bfr[ng], bBase + (uint32_t)((wn + ng*16 + lrow) * LG_ROWB + ks*32 + lcol));
#pragma unroll
            for (int mt = 0; mt < 4; mt++)
#pragma unroll
                for (int nt = 0; nt < 8; nt++) {
                    const int ng = nt >> 1, hi = nt & 1;
                    MMA_BF16(acc[mt][nt], af[mt], bfr[ng][hi], bfr[ng][2 + hi]);
                }
        }
        __syncthreads();
    }

    // epilogue
    const int er = lane >> 2;
    const int ec = (lane & 3) * 2;
#pragma unroll
    for (int mt = 0; mt < 4; mt++) {
        const int rbase = m0 + wm + mt * 16;
#pragma unroll
        for (int nt = 0; nt < 8; nt++) {
            const int col = n0 + wn + nt * 8 + ec;
            *reinterpret_cast<float2*>(C + (size_t)(rbase + er)     * Nglob + col) =
                make_float2(acc[mt][nt][0], acc[mt][nt][1]);
            *reinterpret_cast<float2*>(C + (size_t)(rbase + er + 8) * Nglob + col) =
                make_float2(acc[mt][nt][2], acc[mt][nt][3]);
        }
    }
}

// ======================= bf16 split conversion ===============================
__global__ void split_kernel(const float* __restrict__ src, __nv_bfloat16* __restrict__ dst,
                             int K, int modeA)
{
    long idx = (long)blockIdx.x * blockDim.x + threadIdx.x;
    int m = (int)(idx / K);
    int k = (int)(idx - (long)m * K);
    float v = src[idx];
    __nv_bfloat16 hi = __float2bfloat16_rn(v);
    __nv_bfloat16 lo = __float2bfloat16_rn(v - __bfloat162float(hi));
    __nv_bfloat16* row = dst + (size_t)m * 3 * K;
    row[k]         = hi;
    row[K + k]     = modeA ? lo : hi;
    row[2 * K + k] = modeA ? hi : lo;
}

// ======================= SIMT NT GEMM (small dt/B_proj only) =================
template<int BM, int BN, int BK, int TM, int TN>
__global__ __launch_bounds__((BM/TM)*(BN/TN))
void gemm_nt(const float* __restrict__ A, const float* __restrict__ B,
             float* __restrict__ C, int M, int N, int K)
{
    constexpr int TX = BN / TN;
    constexpr int TY = BM / TM;
    constexpr int NT = TX * TY;
    __shared__ float As[BK][BM];
    __shared__ float Bs[BK][BN];
    const int tid = threadIdx.x;
    const int tx = tid % TX, ty = tid / TX;
    const int m0 = blockIdx.y * BM, n0 = blockIdx.x * BN;
    float acc[TM][TN];
#pragma unroll
    for (int i = 0; i < TM; i++)
#pragma unroll
        for (int j = 0; j < TN; j++) acc[i][j] = 0.f;
    for (int k0 = 0; k0 < K; k0 += BK) {
#pragma unroll
        for (int i = tid; i < BM*BK/4; i += NT) {
            int r = i / (BK/4), c4 = i % (BK/4);
            float4 v = *reinterpret_cast<const float4*>(&A[(size_t)(m0+r)*K + k0 + c4*4]);
            As[c4*4+0][r]=v.x; As[c4*4+1][r]=v.y; As[c4*4+2][r]=v.z; As[c4*4+3][r]=v.w;
        }
#pragma unroll
        for (int i = tid; i < BN*BK/4; i += NT) {
            int r = i / (BK/4), c4 = i % (BK/4);
            float4 v = *reinterpret_cast<const float4*>(&B[(size_t)(n0+r)*K + k0 + c4*4]);
            Bs[c4*4+0][r]=v.x; Bs[c4*4+1][r]=v.y; Bs[c4*4+2][r]=v.z; Bs[c4*4+3][r]=v.w;
        }
        __syncthreads();
#pragma unroll
        for (int k = 0; k < BK; k++) {
            float ar[TM], br[TN];
#pragma unroll
            for (int i = 0; i < TM; i++) ar[i] = As[k][ty*TM+i];
#pragma unroll
            for (int j = 0; j < TN; j++) br[j] = Bs[k][tx*TN+j];
#pragma unroll
            for (int i = 0; i < TM; i++)
#pragma unroll
                for (int j = 0; j < TN; j++) acc[i][j] = fmaf(ar[i], br[j], acc[i][j]);
        }
        __syncthreads();
    }
#pragma unroll
    for (int i = 0; i < TM; i++) {
        float* crow = &C[(size_t)(m0+ty*TM+i)*N + n0 + tx*TN];
#pragma unroll
        for (int j = 0; j < TN; j++) crow[j] = acc[i][j];
    }
}

// ======================= pointwise / aux kernels =============================
__global__ void wcat_kernel(const float* __restrict__ Wx, const float* __restrict__ Wdt)
{
    int idx = blockIdx.x * blockDim.x + threadIdx.x;
    int row = idx >> 10;
    g_wcat[idx] = (row < DSTATE) ? Wdt[idx] : Wx[idx];
}

__global__ void conv_silu_kernel(const float* __restrict__ cw, const float* __restrict__ cb)
{
    int idx = blockIdx.x * blockDim.x + threadIdx.x;
    int c4 = idx & (DINNER/4 - 1);
    int m  = idx >> 8;
    int c  = c4 * 4;
    int l  = m & (SEQLEN - 1);
    float w[4][4];
#pragma unroll
    for (int j = 0; j < 4; j++)
        *reinterpret_cast<float4*>(w[j]) =
            *reinterpret_cast<const float4*>(cw + (size_t)(c + j) * DCONV);
    float4 b = *reinterpret_cast<const float4*>(cb + c);
    float a0 = b.x, a1 = b.y, a2 = b.z, a3 = b.w;
#pragma unroll
    for (int t = 0; t < DCONV; t++) {
        int ls = l - (DCONV - 1) + t;
        if (ls >= 0) {
            float4 xv = *reinterpret_cast<const float4*>(
                g_xr + (size_t)(m - (DCONV - 1) + t) * (2 * DINNER) + c);
            a0 = fmaf(w[0][t], xv.x, a0);
            a1 = fmaf(w[1][t], xv.y, a1);
            a2 = fmaf(w[2][t], xv.z, a2);
            a3 = fmaf(w[3][t], xv.w, a3);
        }
    }
    float4 o;
    o.x = a0 / (1.f + expf(-a0));
    o.y = a1 / (1.f + expf(-a1));
    o.z = a2 / (1.f + expf(-a2));
    o.w = a3 / (1.f + expf(-a3));
    *reinterpret_cast<float4*>(g_xa + (size_t)m * DINNER + c) = o;
}

__global__ void u_kernel()
{
    int gw = (blockIdx.x * blockDim.x + threadIdx.x) >> 5;
    int lane = threadIdx.x & 31;
    if (gw >= M_TOK) return;
    const float* xa = g_xa + (size_t)gw * DINNER;
    float v = xa[lane] + xa[lane + 32];
#pragma unroll
    for (int o = 16; o; o >>= 1) v += __shfl_down_sync(0xffffffffu, v, o);
    if (lane == 0) g_u[gw] = v * (1.f / 64.f);
}

__global__ void dtbu_kernel(const float* __restrict__ bdt, const float* __restrict__ Alog)
{
    int idx = blockIdx.x * blockDim.x + threadIdx.x;
    int m = idx >> 4;
    int n = idx & (DSTATE - 1);
    float raw = g_dtb[(size_t)m * 2 * DSTATE + n] + bdt[n];
    float dt  = raw > 20.f ? raw : log1pf(expf(raw));
    float bp  = g_dtb[(size_t)m * 2 * DSTATE + DSTATE + n];
    float A   = -expf(Alog[n]);
    g_adisc[idx] = expf(A * dt);
    g_bu[idx]    = dt * bp * g_u[m];
}

// -------- chunked scan (3 passes) --------
__global__ void scan_part_kernel()
{
    int t = blockIdx.x * blockDim.x + threadIdx.x;
    int chain = t >> 5, c = t & 31;
    int b = chain >> 4, n = chain & 15;
    size_t base = ((size_t)(b * SEQLEN + c * SCHUNK)) * DSTATE + n;
    float A = 1.f, V = 0.f;
#pragma unroll 8
    for (int i = 0; i < SCHUNK; i++) {
        float a = g_adisc[base + (size_t)i * DSTATE];
        float v = g_bu   [base + (size_t)i * DSTATE];
        V = fmaf(a, V, v);
        A *= a;
    }
    g_cA[chain * NCHUNK + c] = A;
    g_cV[chain * NCHUNK + c] = V;
}
__global__ void scan_mid_kernel()
{
    int chain = threadIdx.x;
    float s = 0.f;
#pragma unroll
    for (int c = 0; c < NCHUNK; c++) {
        g_carry[chain * NCHUNK + c] = s;
        s = fmaf(g_cA[chain * NCHUNK + c], s, g_cV[chain * NCHUNK + c]);
    }
}
__global__ void scan_apply_kernel()
{
    int t = blockIdx.x * blockDim.x + threadIdx.x;
    int chain = t >> 5, c = t & 31;
    int b = chain >> 4, n = chain & 15;
    size_t base = ((size_t)(b * SEQLEN + c * SCHUNK)) * DSTATE + n;
    float s = g_carry[chain * NCHUNK + c];
#pragma unroll 8
    for (int i = 0; i < SCHUNK; i++) {
        float a = g_adisc[base + (size_t)i * DSTATE];
        float v = g_bu   [base + (size_t)i * DSTATE];
        s = fmaf(a, s, v);
        g_y[base + (size_t)i * DSTATE] = s;
    }
}

// -------- gate + skip, fused bf16 split output (A-side: hi|lo|hi) -----------
__global__ void elt_kernel(const float* __restrict__ Dp)
{
    int idx = blockIdx.x * blockDim.x + threadIdx.x;
    int c4 = idx & (DINNER/4 - 1);
    int m  = idx >> 8;
    int c  = c4 * 4;
    float yv  = g_y[(size_t)m * DSTATE + (c >> 6)];
    float4 xa = *reinterpret_cast<const float4*>(g_xa + (size_t)m * DINNER + c);
    float4 D  = *reinterpret_cast<const float4*>(Dp + c);
    float4 r  = *reinterpret_cast<const float4*>(g_xr + (size_t)m * 2 * DINNER + DINNER + c);
    float4 o;
    o.x = (yv + xa.x * D.x) * (r.x / (1.f + expf(-r.x)));
    o.y = (yv + xa.y * D.y) * (r.y / (1.f + expf(-r.y)));
    o.z = (yv + xa.z * D.z) * (r.z / (1.f + expf(-r.z)));
    o.w = (yv + xa.w * D.w) * (r.w / (1.f + expf(-r.w)));

    __nv_bfloat162 h01 = __floats2bfloat162_rn(o.x, o.y);
    __nv_bfloat162 h23 = __floats2bfloat162_rn(o.z, o.w);
    __nv_bfloat162 l01 = __floats2bfloat162_rn(o.x - __bfloat162float(h01.x),
                                               o.y - __bfloat162float(h01.y));
    __nv_bfloat162 l23 = __floats2bfloat162_rn(o.z - __bfloat162float(h23.x),
                                               o.w - __bfloat162float(h23.y));
    __nv_bfloat16* row = g_yb + (size_t)m * 3 * DINNER;
    *reinterpret_cast<__nv_bfloat162*>(row + c)               = h01;
    *reinterpret_cast<__nv_bfloat162*>(row + c + 2)           = h23;
    *reinterpret_cast<__nv_bfloat162*>(row + DINNER + c)      = l01;
    *reinterpret_cast<__nv_bfloat162*>(row + DINNER + c + 2)  = l23;
    *reinterpret_cast<__nv_bfloat162*>(row + 2*DINNER + c)    = h01;
    *reinterpret_cast<__nv_bfloat162*>(row + 2*DINNER + c + 2)= h23;
}

// ======================= launch ==============================================
extern "C" void kernel_launch(void* const* d_in, const int* in_sizes, int n_in,
                              void* d_out, int out_size)
{
    const float* x      = (const float*)d_in[0];
    const float* W_in   = (const float*)d_in[1];
    const float* conv_w = (const float*)d_in[2];
    const float* conv_b = (const float*)d_in[3];
    const float* W_x    = (const float*)d_in[4];
    const float* W_dt   = (const float*)d_in[5];
    const float* b_dt   = (const float*)d_in[6];
    const float* A_log  = (const float*)d_in[7];
    const float* D_par  = (const float*)d_in[8];
    const float* W_out  = (const float*)d_in[9];
    float* out = (float*)d_out;

    float* xr;   cudaGetSymbolAddress((void**)&xr,   g_xr);
    float* xa;   cudaGetSymbolAddress((void**)&xa,   g_xa);
    float* wcat; cudaGetSymbolAddress((void**)&wcat, g_wcat);
    float* dtb;  cudaGetSymbolAddress((void**)&dtb,  g_dtb);
    __nv_bfloat16* xb;  cudaGetSymbolAddress((void**)&xb,  g_xb);
    __nv_bfloat16* wib; cudaGetSymbolAddress((void**)&wib, g_wib);
    __nv_bfloat16* yb;  cudaGetSymbolAddress((void**)&yb,  g_yb);
    __nv_bfloat16* wob; cudaGetSymbolAddress((void**)&wob, g_wob);

    cudaFuncSetAttribute(gemm_hmma, cudaFuncAttributeMaxDynamicSharedMemorySize, GH_SMEM);

    // weight prep
    wcat_kernel<<<(2*DSTATE*DINNER)/256, 256>>>(W_x, W_dt);
    split_kernel<<<(2*DINNER*DIM)/256, 256>>>(W_in, wib, DIM, 0);   // B-side
    split_kernel<<<(DIM*DINNER)/256, 256>>>(W_out, wob, DINNER, 0); // B-side
    split_kernel<<<((long)M_TOK*DIM)/256, 256>>>(x, xb, DIM, 1);    // A-side

    // GEMM1: xr = x @ W_in^T   [16384 x 2048], K''=1536
    gemm_hmma<<<dim3(2*DINNER/128, M_TOK/128), 128, GH_SMEM>>>(
        xb, wib, xr, 2*DINNER, 3*DIM);

    conv_silu_kernel<<<(M_TOK*(DINNER/4))/256, 256>>>(conv_w, conv_b);
    u_kernel<<<(M_TOK*32)/256, 256>>>();

    // small GEMM: [16384 x 32 x 1024] fp32 SIMT
    gemm_nt<64,32,16,4,2><<<dim3(1, M_TOK/64), 256>>>(xa, wcat, dtb, M_TOK, 2*DSTATE, DINNER);

    dtbu_kernel<<<(M_TOK*DSTATE)/256, 256>>>(b_dt, A_log);

    scan_part_kernel<<<(BATCH*DSTATE*NCHUNK)/256, 256>>>();
    scan_mid_kernel<<<1, BATCH*DSTATE>>>();
    scan_apply_kernel<<<(BATCH*DSTATE*NCHUNK)/256, 256>>>();

    elt_kernel<<<(M_TOK*(DINNER/4))/256, 256>>>(D_par);

    // GEMM2: out = y_full @ W_out^T  [16384 x 512], K''=3072
    gemm_hmma<<<dim3(DIM/128, M_TOK/128), 128, GH_SMEM>>>(
        yb, wob, out, DIM, 3*DINNER);
}

// round 5
// speedup vs baseline: 2.9038x; 1.0680x over previous
#include <cuda_runtime.h>
#include <cuda_bf16.h>
#include <math.h>
#include <stdint.h>

#define BATCH   4
#define SEQLEN  4096
#define DIM     512
#define DINNER  1024
#define DSTATE  16
#define DCONV   4
#define M_TOK   (BATCH*SEQLEN)   // 16384

// ======================= PTX helpers (sm_80 baseline) ========================
__device__ __forceinline__ uint32_t smem_to_u32(const void* p) {
    uint32_t a;
    asm("{ .reg .u64 t; cvta.to.shared.u64 t, %1; cvt.u32.u64 %0, t; }"
        : "=r"(a) : "l"(p));
    return a;
}
#define CP_ASYNC16(saddr, gptr) \
    asm volatile("cp.async.cg.shared.global [%0], [%1], 16;" \
        :: "r"(saddr), "l"(gptr))
#define CP_COMMIT() asm volatile("cp.async.commit_group;" ::: "memory")
#define CP_WAIT1()  asm volatile("cp.async.wait_group 1;" ::: "memory")
#define CP_WAIT0()  asm volatile("cp.async.wait_group 0;" ::: "memory")

#define LDSM_X4(r, addr) \
    asm volatile("ldmatrix.sync.aligned.m8n8.x4.shared.b16 {%0,%1,%2,%3}, [%4];" \
        : "=r"((r)[0]), "=r"((r)[1]), "=r"((r)[2]), "=r"((r)[3]) : "r"(addr))

#define MMA_BF16(d, a, b0, b1) \
    asm volatile("mma.sync.aligned.m16n8k16.row.col.f32.bf16.bf16.f32 " \
        "{%0,%1,%2,%3}, {%4,%5,%6,%7}, {%8,%9}, {%0,%1,%2,%3};" \
        : "+f"((d)[0]), "+f"((d)[1]), "+f"((d)[2]), "+f"((d)[3]) \
        : "r"((a)[0]), "r"((a)[1]), "r"((a)[2]), "r"((a)[3]), "r"(b0), "r"(b1))

// ======================= scratch =============================================
__device__ __align__(256) float g_xr  [(size_t)M_TOK * 2 * DINNER];
__device__ __align__(256) float g_xa  [(size_t)M_TOK * DINNER];
__device__ __align__(256) float g_wcat[2 * DSTATE * DINNER];
__device__ __align__(256) float g_dtb [(size_t)M_TOK * 2 * DSTATE];
__device__ __align__(256) float g_u   [M_TOK];
__device__ __align__(256) float g_adisc[(size_t)M_TOK * DSTATE];
__device__ __align__(256) float g_bu  [(size_t)M_TOK * DSTATE];
__device__ __align__(256) float g_y   [(size_t)M_TOK * DSTATE];
// A-side split operands: [hi | lo]  (hi chunk re-read for the 3rd term)
__device__ __align__(256) __nv_bfloat16 g_xb [(size_t)M_TOK * 2 * DIM];     // 32MB
__device__ __align__(256) __nv_bfloat16 g_yb [(size_t)M_TOK * 2 * DINNER];  // 64MB
// B-side split operands: [hi | hi | lo]
__device__ __align__(256) __nv_bfloat16 g_wib[(size_t)2*DINNER * 3 * DIM];
__device__ __align__(256) __nv_bfloat16 g_wob[(size_t)DIM * 3 * DINNER];
// scan chunk summaries
#define SCHUNK  128
#define NCHUNK  (SEQLEN / SCHUNK)   // 32
__device__ float g_cA   [BATCH * DSTATE * NCHUNK];
__device__ float g_cV   [BATCH * DSTATE * NCHUNK];
__device__ float g_carry[BATCH * DSTATE * NCHUNK];

// ======================= HMMA GEMM ===========================================
// C[M,N] = A''[M,Kv] * B''[N,Kv]^T, bf16 K-major, fp32 out.
// A'' is stored [hi|lo] (width 2K); virtual K = 3K with chunk remap
// amap(c) = c < kmod ? c : c - kmod  (kmod = 2K/64).
// Block tile 128x128, 256 threads (8 warps, 4x2, warp tile 32x64),
// K-chunk 64 bf16, cp.async double buffer, ldmatrix + mma.sync.m16n8k16.
#define LG_ROWB   144
#define LG_TILE_B (128 * LG_ROWB)          // 18432 B
#define GH_SMEM   (4 * LG_TILE_B)          // 73728 B

__global__ __launch_bounds__(256, 2)
void gemm_hmma(const __nv_bfloat16* __restrict__ A, const __nv_bfloat16* __restrict__ B,
               float* __restrict__ C, int Nglob, int Kv, int kmod, int Astride)
{
    extern __shared__ char smem[];
    const uint32_t sb = smem_to_u32(smem);
    const int tid  = threadIdx.x;
    const int wid  = tid >> 5;
    const int lane = tid & 31;
    const int m0 = blockIdx.y * 128;
    const int n0 = blockIdx.x * 128;
    const int nch = Kv / 64;

    // warp -> 32(M) x 64(N) sub-tile; warps in 4x2 grid
    const int wm = (wid & 3) * 32;
    const int wn = (wid >> 2) * 64;

    const uint32_t offA[2] = { 0u,              2u * LG_TILE_B };
    const uint32_t offB[2] = { (uint32_t)LG_TILE_B, 3u * LG_TILE_B };

    float acc[2][8][4];
#pragma unroll
    for (int i = 0; i < 2; i++)
#pragma unroll
        for (int j = 0; j < 8; j++)
#pragma unroll
            for (int k = 0; k < 4; k++) acc[i][j][k] = 0.f;

    // async-copy one K-chunk (128 rows x 128B) of A (remapped) and B into buf b
    auto issue = [&](int c, int b) {
        const int ac = (c < kmod) ? c : c - kmod;
        const __nv_bfloat16* Ag = A + (size_t)m0 * Astride + (size_t)ac * 64;
        const __nv_bfloat16* Bg = B + (size_t)n0 * Kv + (size_t)c * 64;
        const uint32_t sa  = sb + offA[b];
        const uint32_t sbm = sb + offB[b];
#pragma unroll
        for (int i = 0; i < 4; i++) {
            int idx = tid + i * 256;              // 0..1023
            int row = idx >> 3, cc = idx & 7;     // 8 x 16B per 128B row
            CP_ASYNC16(sa  + (uint32_t)(row * LG_ROWB + cc * 16),
                       Ag + (size_t)row * Astride + cc * 8);
            CP_ASYNC16(sbm + (uint32_t)(row * LG_ROWB + cc * 16),
                       Bg + (size_t)row * Kv + cc * 8);
        }
        CP_COMMIT();
    };

    issue(0, 0);
    for (int c = 0; c < nch; c++) {
        const int buf = c & 1;
        if (c + 1 < nch) { issue(c + 1, buf ^ 1); CP_WAIT1(); }
        else             { CP_WAIT0(); }
        __syncthreads();

        const uint32_t aBase = sb + offA[buf];
        const uint32_t bBase = sb + offB[buf];
        const int lrow = lane & 15;
        const int lcol = (lane >> 4) * 16;
#pragma unroll
        for (int ks = 0; ks < 4; ks++) {
            uint32_t af[2][4], bfr[4][4];
#pragma unroll
            for (int mt = 0; mt < 2; mt++)
                LDSM_X4(af[mt], aBase + (uint32_t)((wm + mt*16 + lrow) * LG_ROWB + ks*32 + lcol));
#pragma unroll
            for (int ng = 0; ng < 4; ng++)
                LDSM_X4(bfr[ng], bBase + (uint32_t)((wn + ng*16 + lrow) * LG_ROWB + ks*32 + lcol));
#pragma unroll
            for (int mt = 0; mt < 2; mt++)
#pragma unroll
                for (int nt = 0; nt < 8; nt++) {
                    const int ng = nt >> 1, hi = nt & 1;
                    MMA_BF16(acc[mt][nt], af[mt], bfr[ng][hi], bfr[ng][2 + hi]);
                }
        }
        __syncthreads();
    }

    // epilogue
    const int er = lane >> 2;
    const int ec = (lane & 3) * 2;
#pragma unroll
    for (int mt = 0; mt < 2; mt++) {
        const int rbase = m0 + wm + mt * 16;
#pragma unroll
        for (int nt = 0; nt < 8; nt++) {
            const int col = n0 + wn + nt * 8 + ec;
            *reinterpret_cast<float2*>(C + (size_t)(rbase + er)     * Nglob + col) =
                make_float2(acc[mt][nt][0], acc[mt][nt][1]);
            *reinterpret_cast<float2*>(C + (size_t)(rbase + er + 8) * Nglob + col) =
                make_float2(acc[mt][nt][2], acc[mt][nt][3]);
        }
    }
}

// ======================= bf16 split conversions ==============================
// B-side weights: [hi | hi | lo], row width 3K
__global__ void splitw_kernel(const float* __restrict__ src, __nv_bfloat16* __restrict__ dst,
                              int K)
{
    long idx = (long)blockIdx.x * blockDim.x + threadIdx.x;
    int m = (int)(idx / K);
    int k = (int)(idx - (long)m * K);
    float v = src[idx];
    __nv_bfloat16 hi = __float2bfloat16_rn(v);
    __nv_bfloat16 lo = __float2bfloat16_rn(v - __bfloat162float(hi));
    __nv_bfloat16* row = dst + (size_t)m * 3 * K;
    row[k]         = hi;
    row[K + k]     = hi;
    row[2 * K + k] = lo;
}
// A-side: [hi | lo], row width 2K
__global__ void splita_kernel(const float* __restrict__ src, __nv_bfloat16* __restrict__ dst,
                              int K)
{
    long idx = (long)blockIdx.x * blockDim.x + threadIdx.x;
    int m = (int)(idx / K);
    int k = (int)(idx - (long)m * K);
    float v = src[idx];
    __nv_bfloat16 hi = __float2bfloat16_rn(v);
    __nv_bfloat16 lo = __float2bfloat16_rn(v - __bfloat162float(hi));
    __nv_bfloat16* row = dst + (size_t)m * 2 * K;
    row[k]     = hi;
    row[K + k] = lo;
}

// ======================= SIMT NT GEMM (small dt/B_proj only) =================
template<int BM, int BN, int BK, int TM, int TN>
__global__ __launch_bounds__((BM/TM)*(BN/TN))
void gemm_nt(const float* __restrict__ A, const float* __restrict__ B,
             float* __restrict__ C, int M, int N, int K)
{
    constexpr int TX = BN / TN;
    constexpr int TY = BM / TM;
    constexpr int NT = TX * TY;
    __shared__ float As[BK][BM];
    __shared__ float Bs[BK][BN];
    const int tid = threadIdx.x;
    const int tx = tid % TX, ty = tid / TX;
    const int m0 = blockIdx.y * BM, n0 = blockIdx.x * BN;
    float acc[TM][TN];
#pragma unroll
    for (int i = 0; i < TM; i++)
#pragma unroll
        for (int j = 0; j < TN; j++) acc[i][j] = 0.f;
    for (int k0 = 0; k0 < K; k0 += BK) {
#pragma unroll
        for (int i = tid; i < BM*BK/4; i += NT) {
            int r = i / (BK/4), c4 = i % (BK/4);
            float4 v = *reinterpret_cast<const float4*>(&A[(size_t)(m0+r)*K + k0 + c4*4]);
            As[c4*4+0][r]=v.x; As[c4*4+1][r]=v.y; As[c4*4+2][r]=v.z; As[c4*4+3][r]=v.w;
        }
#pragma unroll
        for (int i = tid; i < BN*BK/4; i += NT) {
            int r = i / (BK/4), c4 = i % (BK/4);
            float4 v = *reinterpret_cast<const float4*>(&B[(size_t)(n0+r)*K + k0 + c4*4]);
            Bs[c4*4+0][r]=v.x; Bs[c4*4+1][r]=v.y; Bs[c4*4+2][r]=v.z; Bs[c4*4+3][r]=v.w;
        }
        __syncthreads();
#pragma unroll
        for (int k = 0; k < BK; k++) {
            float ar[TM], br[TN];
#pragma unroll
            for (int i = 0; i < TM; i++) ar[i] = As[k][ty*TM+i];
#pragma unroll
            for (int j = 0; j < TN; j++) br[j] = Bs[k][tx*TN+j];
#pragma unroll
            for (int i = 0; i < TM; i++)
#pragma unroll
                for (int j = 0; j < TN; j++) acc[i][j] = fmaf(ar[i], br[j], acc[i][j]);
        }
        __syncthreads();
    }
#pragma unroll
    for (int i = 0; i < TM; i++) {
        float* crow = &C[(size_t)(m0+ty*TM+i)*N + n0 + tx*TN];
#pragma unroll
        for (int j = 0; j < TN; j++) crow[j] = acc[i][j];
    }
}

// ======================= pointwise / aux kernels =============================
__global__ void wcat_kernel(const float* __restrict__ Wx, const float* __restrict__ Wdt)
{
    int idx = blockIdx.x * blockDim.x + threadIdx.x;
    int row = idx >> 10;
    g_wcat[idx] = (row < DSTATE) ? Wdt[idx] : Wx[idx];
}

__global__ void conv_silu_kernel(const float* __restrict__ cw, const float* __restrict__ cb)
{
    int idx = blockIdx.x * blockDim.x + threadIdx.x;
    int c4 = idx & (DINNER/4 - 1);
    int m  = idx >> 8;
    int c  = c4 * 4;
    int l  = m & (SEQLEN - 1);
    float w[4][4];
#pragma unroll
    for (int j = 0; j < 4; j++)
        *reinterpret_cast<float4*>(w[j]) =
            *reinterpret_cast<const float4*>(cw + (size_t)(c + j) * DCONV);
    float4 b = *reinterpret_cast<const float4*>(cb + c);
    float a0 = b.x, a1 = b.y, a2 = b.z, a3 = b.w;
#pragma unroll
    for (int t = 0; t < DCONV; t++) {
        int ls = l - (DCONV - 1) + t;
        if (ls >= 0) {
            float4 xv = *reinterpret_cast<const float4*>(
                g_xr + (size_t)(m - (DCONV - 1) + t) * (2 * DINNER) + c);
            a0 = fmaf(w[0][t], xv.x, a0);
            a1 = fmaf(w[1][t], xv.y, a1);
            a2 = fmaf(w[2][t], xv.z, a2);
            a3 = fmaf(w[3][t], xv.w, a3);
        }
    }
    float4 o;
    o.x = a0 / (1.f + expf(-a0));
    o.y = a1 / (1.f + expf(-a1));
    o.z = a2 / (1.f + expf(-a2));
    o.w = a3 / (1.f + expf(-a3));
    *reinterpret_cast<float4*>(g_xa + (size_t)m * DINNER + c) = o;
}

__global__ void u_kernel()
{
    int gw = (blockIdx.x * blockDim.x + threadIdx.x) >> 5;
    int lane = threadIdx.x & 31;
    if (gw >= M_TOK) return;
    const float* xa = g_xa + (size_t)gw * DINNER;
    float v = xa[lane] + xa[lane + 32];
#pragma unroll
    for (int o = 16; o; o >>= 1) v += __shfl_down_sync(0xffffffffu, v, o);
    if (lane == 0) g_u[gw] = v * (1.f / 64.f);
}

__global__ void dtbu_kernel(const float* __restrict__ bdt, const float* __restrict__ Alog)
{
    int idx = blockIdx.x * blockDim.x + threadIdx.x;
    int m = idx >> 4;
    int n = idx & (DSTATE - 1);
    float raw = g_dtb[(size_t)m * 2 * DSTATE + n] + bdt[n];
    float dt  = raw > 20.f ? raw : log1pf(expf(raw));
    float bp  = g_dtb[(size_t)m * 2 * DSTATE + DSTATE + n];
    float A   = -expf(Alog[n]);
    g_adisc[idx] = expf(A * dt);
    g_bu[idx]    = dt * bp * g_u[m];
}

// -------- chunked scan (3 passes) --------
__global__ void scan_part_kernel()
{
    int t = blockIdx.x * blockDim.x + threadIdx.x;
    int chain = t >> 5, c = t & 31;
    int b = chain >> 4, n = chain & 15;
    size_t base = ((size_t)(b * SEQLEN + c * SCHUNK)) * DSTATE + n;
    float A = 1.f, V = 0.f;
#pragma unroll 8
    for (int i = 0; i < SCHUNK; i++) {
        float a = g_adisc[base + (size_t)i * DSTATE];
        float v = g_bu   [base + (size_t)i * DSTATE];
        V = fmaf(a, V, v);
        A *= a;
    }
    g_cA[chain * NCHUNK + c] = A;
    g_cV[chain * NCHUNK + c] = V;
}
__global__ void scan_mid_kernel()
{
    int chain = threadIdx.x;
    float s = 0.f;
#pragma unroll
    for (int c = 0; c < NCHUNK; c++) {
        g_carry[chain * NCHUNK + c] = s;
        s = fmaf(g_cA[chain * NCHUNK + c], s, g_cV[chain * NCHUNK + c]);
    }
}
__global__ void scan_apply_kernel()
{
    int t = blockIdx.x * blockDim.x + threadIdx.x;
    int chain = t >> 5, c = t & 31;
    int b = chain >> 4, n = chain & 15;
    size_t base = ((size_t)(b * SEQLEN + c * SCHUNK)) * DSTATE + n;
    float s = g_carry[chain * NCHUNK + c];
#pragma unroll 8
    for (int i = 0; i < SCHUNK; i++) {
        float a = g_adisc[base + (size_t)i * DSTATE];
        float v = g_bu   [base + (size_t)i * DSTATE];
        s = fmaf(a, s, v);
        g_y[base + (size_t)i * DSTATE] = s;
    }
}

// -------- gate + skip, fused bf16 [hi|lo] split output -----------------------
__global__ void elt_kernel(const float* __restrict__ Dp)
{
    int idx = blockIdx.x * blockDim.x + threadIdx.x;
    int c4 = idx & (DINNER/4 - 1);
    int m  = idx >> 8;
    int c  = c4 * 4;
    float yv  = g_y[(size_t)m * DSTATE + (c >> 6)];
    float4 xa = *reinterpret_cast<const float4*>(g_xa + (size_t)m * DINNER + c);
    float4 D  = *reinterpret_cast<const float4*>(Dp + c);
    float4 r  = *reinterpret_cast<const float4*>(g_xr + (size_t)m * 2 * DINNER + DINNER + c);
    float4 o;
    o.x = (yv + xa.x * D.x) * (r.x / (1.f + expf(-r.x)));
    o.y = (yv + xa.y * D.y) * (r.y / (1.f + expf(-r.y)));
    o.z = (yv + xa.z * D.z) * (r.z / (1.f + expf(-r.z)));
    o.w = (yv + xa.w * D.w) * (r.w / (1.f + expf(-r.w)));

    __nv_bfloat162 h01 = __floats2bfloat162_rn(o.x, o.y);
    __nv_bfloat162 h23 = __floats2bfloat162_rn(o.z, o.w);
    __nv_bfloat162 l01 = __floats2bfloat162_rn(o.x - __bfloat162float(h01.x),
                                               o.y - __bfloat162float(h01.y));
    __nv_bfloat162 l23 = __floats2bfloat162_rn(o.z - __bfloat162float(h23.x),
                                               o.w - __bfloat162float(h23.y));
    __nv_bfloat16* row = g_yb + (size_t)m * 2 * DINNER;
    *reinterpret_cast<__nv_bfloat162*>(row + c)              = h01;
    *reinterpret_cast<__nv_bfloat162*>(row + c + 2)          = h23;
    *reinterpret_cast<__nv_bfloat162*>(row + DINNER + c)     = l01;
    *reinterpret_cast<__nv_bfloat162*>(row + DINNER + c + 2) = l23;
}

// ======================= launch ==============================================
extern "C" void kernel_launch(void* const* d_in, const int* in_sizes, int n_in,
                              void* d_out, int out_size)
{
    const float* x      = (const float*)d_in[0];
    const float* W_in   = (const float*)d_in[1];
    const float* conv_w = (const float*)d_in[2];
    const float* conv_b = (const float*)d_in[3];
    const float* W_x    = (const float*)d_in[4];
    const float* W_dt   = (const float*)d_in[5];
    const float* b_dt   = (const float*)d_in[6];
    const float* A_log  = (const float*)d_in[7];
    const float* D_par  = (const float*)d_in[8];
    const float* W_out  = (const float*)d_in[9];
    float* out = (float*)d_out;

    float* xr;   cudaGetSymbolAddress((void**)&xr,   g_xr);
    float* xa;   cudaGetSymbolAddress((void**)&xa,   g_xa);
    float* wcat; cudaGetSymbolAddress((void**)&wcat, g_wcat);
    float* dtb;  cudaGetSymbolAddress((void**)&dtb,  g_dtb);
    __nv_bfloat16* xb;  cudaGetSymbolAddress((void**)&xb,  g_xb);
    __nv_bfloat16* wib; cudaGetSymbolAddress((void**)&wib, g_wib);
    __nv_bfloat16* yb;  cudaGetSymbolAddress((void**)&yb,  g_yb);
    __nv_bfloat16* wob; cudaGetSymbolAddress((void**)&wob, g_wob);

    cudaFuncSetAttribute(gemm_hmma, cudaFuncAttributeMaxDynamicSharedMemorySize, GH_SMEM);

    // weight prep
    wcat_kernel<<<(2*DSTATE*DINNER)/256, 256>>>(W_x, W_dt);
    splitw_kernel<<<(2*DINNER*DIM)/256, 256>>>(W_in, wib, DIM);
    splitw_kernel<<<(DIM*DINNER)/256, 256>>>(W_out, wob, DINNER);
    splita_kernel<<<((long)M_TOK*DIM)/256, 256>>>(x, xb, DIM);

    // GEMM1: xr = x @ W_in^T   [16384 x 2048], Kv=1536, kmod=16, Astride=1024
    gemm_hmma<<<dim3(2*DINNER/128, M_TOK/128), 256, GH_SMEM>>>(
        xb, wib, xr, 2*DINNER, 3*DIM, (2*DIM)/64, 2*DIM);

    conv_silu_kernel<<<(M_TOK*(DINNER/4))/256, 256>>>(conv_w, conv_b);
    u_kernel<<<(M_TOK*32)/256, 256>>>();

    // small GEMM: [16384 x 32 x 1024] fp32 SIMT
    gemm_nt<64,32,16,4,2><<<dim3(1, M_TOK/64), 256>>>(xa, wcat, dtb, M_TOK, 2*DSTATE, DINNER);

    dtbu_kernel<<<(M_TOK*DSTATE)/256, 256>>>(b_dt, A_log);

    scan_part_kernel<<<(BATCH*DSTATE*NCHUNK)/256, 256>>>();
    scan_mid_kernel<<<1, BATCH*DSTATE>>>();
    scan_apply_kernel<<<(BATCH*DSTATE*NCHUNK)/256, 256>>>();

    elt_kernel<<<(M_TOK*(DINNER/4))/256, 256>>>(D_par);

    // GEMM2: out = y_full @ W_out^T  [16384 x 512], Kv=3072, kmod=32, Astride=2048
    gemm_hmma<<<dim3(DIM/128, M_TOK/128), 256, GH_SMEM>>>(
        yb, wob, out, DIM, 3*DINNER, (2*DINNER)/64, 2*DINNER);
}

// round 6
// speedup vs baseline: 2.9222x; 1.0063x over previous
#include <cuda_runtime.h>
#include <cuda_bf16.h>
#include <math.h>
#include <stdint.h>

#define BATCH   4
#define SEQLEN  4096
#define DIM     512
#define DINNER  1024
#define DSTATE  16
#define DCONV   4
#define M_TOK   (BATCH*SEQLEN)   // 16384

// ======================= PTX helpers (declared unconditionally) ==============
// Macros only expand where used; the tcgen05 ones are used solely inside the
// __CUDA_ARCH_FEAT_SM103_ALL-guarded kernel body, so the plain compute_103
// pass never sees tcgen05 PTX.
__device__ __forceinline__ uint32_t smem_to_u32(const void* p) {
    uint32_t a;
    asm("{ .reg .u64 t; cvta.to.shared.u64 t, %1; cvt.u32.u64 %0, t; }"
        : "=r"(a) : "l"(p));
    return a;
}
__device__ __forceinline__ uint32_t elect_one_pred() {   // sm_90 baseline
    uint32_t pred;
    asm volatile("{\n\t.reg .pred p;\n\telect.sync _|p, 0xFFFFFFFF;\n\t"
                 "selp.b32 %0, 1, 0, p;\n\t}" : "=r"(pred));
    return pred;
}
#define CP_ASYNC16(saddr, gptr) \
    asm volatile("cp.async.cg.shared.global [%0], [%1], 16;" \
        :: "r"(saddr), "l"(gptr))
#define CP_COMMIT() asm volatile("cp.async.commit_group;" ::: "memory")
#define CP_WAIT1()  asm volatile("cp.async.wait_group 1;" ::: "memory")
#define CP_WAIT0()  asm volatile("cp.async.wait_group 0;" ::: "memory")

#define LDSM_X4(r, addr) \
    asm volatile("ldmatrix.sync.aligned.m8n8.x4.shared.b16 {%0,%1,%2,%3}, [%4];" \
        : "=r"((r)[0]), "=r"((r)[1]), "=r"((r)[2]), "=r"((r)[3]) : "r"(addr))

#define MMA_BF16(d, a, b0, b1) \
    asm volatile("mma.sync.aligned.m16n8k16.row.col.f32.bf16.bf16.f32 " \
        "{%0,%1,%2,%3}, {%4,%5,%6,%7}, {%8,%9}, {%0,%1,%2,%3};" \
        : "+f"((d)[0]), "+f"((d)[1]), "+f"((d)[2]), "+f"((d)[3]) \
        : "r"((a)[0]), "r"((a)[1]), "r"((a)[2]), "r"((a)[3]), "r"(b0), "r"(b1))

#define MBARRIER_INIT(mbar, count) \
    asm volatile("mbarrier.init.shared.b64 [%0], %1;" \
        :: "r"((uint32_t)(mbar)), "r"((uint32_t)(count)) : "memory")
#define MBARRIER_INVAL(mbar) \
    asm volatile("mbarrier.inval.shared.b64 [%0];" :: "r"((uint32_t)(mbar)) : "memory")
#define MBARRIER_WAIT_PARITY(mbar, parity) do { \
    uint32_t _m = (uint32_t)(mbar); uint32_t _p = (uint32_t)(parity); uint32_t _d; \
    asm volatile("{\n\t.reg .pred p;\n\t" \
        "mbarrier.try_wait.parity.acquire.cta.shared::cta.b64 p, [%1], %2;\n\t" \
        "selp.b32 %0, 1, 0, p;\n\t}" : "=r"(_d) : "r"(_m), "r"(_p) : "memory"); \
    if (!_d) { \
        asm volatile("{\n\t.reg .pred P1;\n\t" \
            "WL_%=:\n\t" \
            "mbarrier.try_wait.parity.acquire.cta.shared::cta.b64 P1, [%0], %1, 0x989680;\n\t" \
            "@P1 bra.uni WD_%=;\n\tbra.uni WL_%=;\n\tWD_%=:\n\t}" \
            :: "r"(_m), "r"(_p) : "memory"); \
    } } while(0)

#define TCGEN05_ALLOC(smem_addr, nCols) \
    asm volatile("tcgen05.alloc.cta_group::1.sync.aligned.shared::cta.b32 [%0], %1;" \
        :: "r"((uint32_t)(smem_addr)), "r"((uint32_t)(nCols)) : "memory")
#define TCGEN05_DEALLOC(tmem, nCols) \
    asm volatile("tcgen05.dealloc.cta_group::1.sync.aligned.b32 %0, %1;" \
        :: "r"(tmem), "r"((uint32_t)(nCols)))
#define TCGEN05_RELINQUISH() \
    asm volatile("tcgen05.relinquish_alloc_permit.cta_group::1.sync.aligned;")
#define TCGEN05_COMMIT(mbar) \
    asm volatile("tcgen05.commit.cta_group::1.mbarrier::arrive::one.shared::cluster.b64 [%0];" \
        :: "r"((uint32_t)(mbar)) : "memory")
#define TCGEN05_FENCE_BEFORE() \
    asm volatile("tcgen05.fence::before_thread_sync;" ::: "memory")
#define TCGEN05_FENCE_AFTER() \
    asm volatile("tcgen05.fence::after_thread_sync;" ::: "memory")
#define TCGEN05_WAIT_LD() \
    asm volatile("tcgen05.wait::ld.sync.aligned;" ::: "memory")
#define FENCE_PROXY_ASYNC_SHARED_CTA() \
    asm volatile("fence.proxy.async.shared::cta;" ::: "memory")
#define TCGEN05_LD_32X32B_X32(r, tmem_addr) \
    asm volatile("tcgen05.ld.sync.aligned.32x32b.x32.b32 " \
        "{%0, %1, %2, %3, %4, %5, %6, %7, %8, %9, %10, %11, %12, %13, %14, %15, " \
        " %16, %17, %18, %19, %20, %21, %22, %23, %24, %25, %26, %27, %28, %29, %30, %31}, [%32];" \
        : "=r"((r)[0]),  "=r"((r)[1]),  "=r"((r)[2]),  "=r"((r)[3]), \
          "=r"((r)[4]),  "=r"((r)[5]),  "=r"((r)[6]),  "=r"((r)[7]), \
          "=r"((r)[8]),  "=r"((r)[9]),  "=r"((r)[10]), "=r"((r)[11]), \
          "=r"((r)[12]), "=r"((r)[13]), "=r"((r)[14]), "=r"((r)[15]), \
          "=r"((r)[16]), "=r"((r)[17]), "=r"((r)[18]), "=r"((r)[19]), \
          "=r"((r)[20]), "=r"((r)[21]), "=r"((r)[22]), "=r"((r)[23]), \
          "=r"((r)[24]), "=r"((r)[25]), "=r"((r)[26]), "=r"((r)[27]), \
          "=r"((r)[28]), "=r"((r)[29]), "=r"((r)[30]), "=r"((r)[31]) \
        : "r"(tmem_addr))

#define TCGEN05_MMA_BF16_SS(d_tmem, a_desc, b_desc, idesc, en) \
    asm volatile( \
        "{\n\t.reg .pred p;\n\tsetp.ne.u32 p, %5, 0;\n\t" \
        "tcgen05.mma.cta_group::1.kind::f16 [%0], %1, %2, %3, {%4, %4, %4, %4}, p;\n\t}" \
        :: "r"(d_tmem), "l"(a_desc), "l"(b_desc), "r"(idesc), "r"(0u), "r"((uint32_t)(en)) \
        : "memory")

// plain constexpr: identical in all passes, no arch dependence at file scope
static constexpr uint64_t SMEM_DESC_BASE_SW128 =
    (uint64_t(2)  << 61) | (uint64_t(1) << 46) | (uint64_t(64) << 32) | (uint64_t(1) << 16);
#define MAKE_SMEM_DESC(base_addr) \
    (SMEM_DESC_BASE_SW128 | ((uint64_t)((base_addr) >> 4) & 0x3FFF))
// idesc: fp32 accum, bf16 A/B, N=128, M=128
static constexpr uint32_t GT_IDESC =
    (1u << 4) | (1u << 7) | (1u << 10) | ((128u / 8) << 17) | ((128u / 16) << 24);

// ======================= scratch =============================================
__device__ __align__(256) float g_xr  [(size_t)M_TOK * 2 * DINNER];
__device__ __align__(256) float g_xa  [(size_t)M_TOK * DINNER];
__device__ __align__(256) float g_wcat[2 * DSTATE * DINNER];
__device__ __align__(256) float g_dtb [(size_t)M_TOK * 2 * DSTATE];
__device__ __align__(256) float g_u   [M_TOK];
__device__ __align__(256) float g_adisc[(size_t)M_TOK * DSTATE];
__device__ __align__(256) float g_bu  [(size_t)M_TOK * DSTATE];
__device__ __align__(256) float g_y   [(size_t)M_TOK * DSTATE];
// A-side split operands: [hi | lo]  (hi chunk re-read for the 3rd term)
__device__ __align__(256) __nv_bfloat16 g_xb [(size_t)M_TOK * 2 * DIM];
__device__ __align__(256) __nv_bfloat16 g_yb [(size_t)M_TOK * 2 * DINNER];
// B-side split operands: [hi | hi | lo]
__device__ __align__(256) __nv_bfloat16 g_wib[(size_t)2*DINNER * 3 * DIM];
__device__ __align__(256) __nv_bfloat16 g_wob[(size_t)DIM * 3 * DINNER];
// scan chunk summaries
#define SCHUNK  128
#define NCHUNK  (SEQLEN / SCHUNK)   // 32
__device__ float g_cA   [BATCH * DSTATE * NCHUNK];
__device__ float g_cV   [BATCH * DSTATE * NCHUNK];
__device__ float g_carry[BATCH * DSTATE * NCHUNK];

// ======================= dual-path GEMM ======================================
// C[M,N] = A''[M,3K] * B''[N,3K]^T, bf16 K-major, fp32 out.
// A'' stored [hi|lo] (width 2K); chunk remap amap(c)= c<kmod ? c : c-kmod.
// Block tile 128x128, 256 threads, K-chunk 64 bf16.
// sm_103a cubin: tcgen05 SS MMA, TMEM accum, double-buffered smem.
// otherwise:     ldmatrix + mma.sync.m16n8k16 (8 warps, 4x2).
#define LG_ROWB   144
#define LG_TILE_B (128 * LG_ROWB)          // 18432 B
#define GH_SMEM   (4 * LG_TILE_B)          // 73728 B  (covers both paths)

// tcgen05-path offsets within the dynamic smem buffer
#define GT_TMEM 0
#define GT_MB   8
#define GT_A0   1024
#define GT_A1   (GT_A0 + 16384)
#define GT_B0   (GT_A1 + 16384)
#define GT_B1   (GT_B0 + 16384)

__global__ __launch_bounds__(256, 2)
void gemm_dual(const __nv_bfloat16* __restrict__ A, const __nv_bfloat16* __restrict__ B,
               float* __restrict__ C, int Nglob, int Kv, int kmod, int Astride)
{
    extern __shared__ char smem[];
    const uint32_t sb = smem_to_u32(smem);
    const int tid  = threadIdx.x;
    const int wid  = tid >> 5;
    const int lane = tid & 31;
    const int m0 = blockIdx.y * 128;
    const int n0 = blockIdx.x * 128;
    const int nch = Kv / 64;

#if defined(__CUDA_ARCH_FEAT_SM103_ALL)
    // ---------------------------- tcgen05 path ------------------------------
    if (wid == 0) TCGEN05_ALLOC(sb + GT_TMEM, 128);
    if (tid == 0) {
        MBARRIER_INIT(sb + GT_MB,     1);
        MBARRIER_INIT(sb + GT_MB + 8, 1);
    }
    __syncthreads();
    uint32_t tmem;
    asm volatile("ld.shared.b32 %0, [%1];" : "=r"(tmem) : "r"(sb + GT_TMEM));

    const uint32_t offA[2] = {GT_A0, GT_A1};
    const uint32_t offB[2] = {GT_B0, GT_B1};
    int ph[2] = {0, 0};

    for (int c = 0; c < nch; c++) {
        const int buf = c & 1;
        if (c >= 2) { MBARRIER_WAIT_PARITY(sb + GT_MB + buf * 8, ph[buf]); ph[buf] ^= 1; }

        const int ac = (c < kmod) ? c : c - kmod;
        const __nv_bfloat16* Ab = A + (size_t)m0 * Astride + (size_t)ac * 64;
        const __nv_bfloat16* Bb = B + (size_t)n0 * Kv + (size_t)c * 64;
        char* smA = smem + offA[buf];
        char* smB = smem + offB[buf];
        // 256 threads fill 128 rows x 128B for A and B (SW128 swizzled)
#pragma unroll
        for (int i = 0; i < 4; i++) {
            int e = tid + i * 256;
            int r = e >> 3, s = e & 7;
            uint4 va = *reinterpret_cast<const uint4*>(Ab + (size_t)r * Astride + s * 8);
            uint32_t off = (uint32_t)(r * 128 + s * 16);
            *reinterpret_cast<uint4*>(smA + (off ^ ((off >> 3) & 0x70))) = va;
            uint4 vb = *reinterpret_cast<const uint4*>(Bb + (size_t)r * Kv + s * 8);
            *reinterpret_cast<uint4*>(smB + (off ^ ((off >> 3) & 0x70))) = vb;
        }
        FENCE_PROXY_ASYNC_SHARED_CTA();
        __syncthreads();

        if (wid == 0) {
            if (elect_one_pred()) {
                TCGEN05_FENCE_AFTER();
                uint64_t da = MAKE_SMEM_DESC(sb + offA[buf]);
                uint64_t db = MAKE_SMEM_DESC(sb + offB[buf]);
#pragma unroll
                for (int kk = 0; kk < 4; kk++)
                    TCGEN05_MMA_BF16_SS(tmem, da + kk * 2, db + kk * 2, GT_IDESC,
                                        (c == 0 && kk == 0) ? 0u : 1u);
                TCGEN05_COMMIT(sb + GT_MB + buf * 8);
            }
        }
    }
    {
        const int lb = (nch - 1) & 1;
        MBARRIER_WAIT_PARITY(sb + GT_MB + lb * 8, ph[lb]);
    }
    TCGEN05_FENCE_AFTER();

    // epilogue: warps 0-3 read the 128x128 fp32 accumulator from TMEM
    if (wid < 4) {
        uint32_t r[32];
        const int row = m0 + wid * 32 + lane;
#pragma unroll
        for (int c0 = 0; c0 < 128; c0 += 32) {
            TCGEN05_LD_32X32B_X32(r, tmem + c0);
            TCGEN05_WAIT_LD();
            TCGEN05_FENCE_BEFORE();
            float* crow = C + (size_t)row * Nglob + n0 + c0;
#pragma unroll
            for (int j = 0; j < 8; j++)
                *reinterpret_cast<float4*>(crow + j * 4) =
                    make_float4(__uint_as_float(r[j*4+0]), __uint_as_float(r[j*4+1]),
                                __uint_as_float(r[j*4+2]), __uint_as_float(r[j*4+3]));
        }
    }
    __syncthreads();
    if (tid == 0) { MBARRIER_INVAL(sb + GT_MB); MBARRIER_INVAL(sb + GT_MB + 8); }
    __syncthreads();
    if (wid == 0) { TCGEN05_RELINQUISH(); TCGEN05_DEALLOC(tmem, 128); }
#else
    // ---------------------------- legacy HMMA path --------------------------
    const int wm = (wid & 3) * 32;
    const int wn = (wid >> 2) * 64;
    const uint32_t offA[2] = { 0u,              2u * LG_TILE_B };
    const uint32_t offB[2] = { (uint32_t)LG_TILE_B, 3u * LG_TILE_B };

    float acc[2][8][4];
#pragma unroll
    for (int i = 0; i < 2; i++)
#pragma unroll
        for (int j = 0; j < 8; j++)
#pragma unroll
            for (int k = 0; k < 4; k++) acc[i][j][k] = 0.f;

    auto issue = [&](int c, int b) {
        const int ac = (c < kmod) ? c : c - kmod;
        const __nv_bfloat16* Ag = A + (size_t)m0 * Astride + (size_t)ac * 64;
        const __nv_bfloat16* Bg = B + (size_t)n0 * Kv + (size_t)c * 64;
        const uint32_t sa  = sb + offA[b];
        const uint32_t sbm = sb + offB[b];
#pragma unroll
        for (int i = 0; i < 4; i++) {
            int idx = tid + i * 256;
            int row = idx >> 3, cc = idx & 7;
            CP_ASYNC16(sa  + (uint32_t)(row * LG_ROWB + cc * 16),
                       Ag + (size_t)row * Astride + cc * 8);
            CP_ASYNC16(sbm + (uint32_t)(row * LG_ROWB + cc * 16),
                       Bg + (size_t)row * Kv + cc * 8);
        }
        CP_COMMIT();
    };

    issue(0, 0);
    for (int c = 0; c < nch; c++) {
        const int buf = c & 1;
        if (c + 1 < nch) { issue(c + 1, buf ^ 1); CP_WAIT1(); }
        else             { CP_WAIT0(); }
        __syncthreads();

        const uint32_t aBase = sb + offA[buf];
        const uint32_t bBase = sb + offB[buf];
        const int lrow = lane & 15;
        const int lcol = (lane >> 4) * 16;
#pragma unroll
        for (int ks = 0; ks < 4; ks++) {
            uint32_t af[2][4], bfr[4][4];
#pragma unroll
            for (int mt = 0; mt < 2; mt++)
                LDSM_X4(af[mt], aBase + (uint32_t)((wm + mt*16 + lrow) * LG_ROWB + ks*32 + lcol));
#pragma unroll
            for (int ng = 0; ng < 4; ng++)
                LDSM_X4(bfr[ng], bBase + (uint32_t)((wn + ng*16 + lrow) * LG_ROWB + ks*32 + lcol));
#pragma unroll
            for (int mt = 0; mt < 2; mt++)
#pragma unroll
                for (int nt = 0; nt < 8; nt++) {
                    const int ng = nt >> 1, hi = nt & 1;
                    MMA_BF16(acc[mt][nt], af[mt], bfr[ng][hi], bfr[ng][2 + hi]);
                }
        }
        __syncthreads();
    }

    const int er = lane >> 2;
    const int ec = (lane & 3) * 2;
#pragma unroll
    for (int mt = 0; mt < 2; mt++) {
        const int rbase = m0 + wm + mt * 16;
#pragma unroll
        for (int nt = 0; nt < 8; nt++) {
            const int col = n0 + wn + nt * 8 + ec;
            *reinterpret_cast<float2*>(C + (size_t)(rbase + er)     * Nglob + col) =
                make_float2(acc[mt][nt][0], acc[mt][nt][1]);
            *reinterpret_cast<float2*>(C + (size_t)(rbase + er + 8) * Nglob + col) =
                make_float2(acc[mt][nt][2], acc[mt][nt][3]);
        }
    }
#endif
}

// ======================= bf16 split conversions ==============================
__global__ void splitw_kernel(const float* __restrict__ src, __nv_bfloat16* __restrict__ dst,
                              int K)
{
    long idx = (long)blockIdx.x * blockDim.x + threadIdx.x;
    int m = (int)(idx / K);
    int k = (int)(idx - (long)m * K);
    float v = src[idx];
    __nv_bfloat16 hi = __float2bfloat16_rn(v);
    __nv_bfloat16 lo = __float2bfloat16_rn(v - __bfloat162float(hi));
    __nv_bfloat16* row = dst + (size_t)m * 3 * K;
    row[k]         = hi;
    row[K + k]     = hi;
    row[2 * K + k] = lo;
}
__global__ void splita_kernel(const float* __restrict__ src, __nv_bfloat16* __restrict__ dst,
                              int K)
{
    long idx = (long)blockIdx.x * blockDim.x + threadIdx.x;
    int m = (int)(idx / K);
    int k = (int)(idx - (long)m * K);
    float v = src[idx];
    __nv_bfloat16 hi = __float2bfloat16_rn(v);
    __nv_bfloat16 lo = __float2bfloat16_rn(v - __bfloat162float(hi));
    __nv_bfloat16* row = dst + (size_t)m * 2 * K;
    row[k]     = hi;
    row[K + k] = lo;
}

// ======================= SIMT NT GEMM (small dt/B_proj only) =================
template<int BM, int BN, int BK, int TM, int TN>
__global__ __launch_bounds__((BM/TM)*(BN/TN))
void gemm_nt(const float* __restrict__ A, const float* __restrict__ B,
             float* __restrict__ C, int M, int N, int K)
{
    constexpr int TX = BN / TN;
    constexpr int TY = BM / TM;
    constexpr int NT = TX * TY;
    __shared__ float As[BK][BM];
    __shared__ float Bs[BK][BN];
    const int tid = threadIdx.x;
    const int tx = tid % TX, ty = tid / TX;
    const int m0 = blockIdx.y * BM, n0 = blockIdx.x * BN;
    float acc[TM][TN];
#pragma unroll
    for (int i = 0; i < TM; i++)
#pragma unroll
        for (int j = 0; j < TN; j++) acc[i][j] = 0.f;
    for (int k0 = 0; k0 < K; k0 += BK) {
#pragma unroll
        for (int i = tid; i < BM*BK/4; i += NT) {
            int r = i / (BK/4), c4 = i % (BK/4);
            float4 v = *reinterpret_cast<const float4*>(&A[(size_t)(m0+r)*K + k0 + c4*4]);
            As[c4*4+0][r]=v.x; As[c4*4+1][r]=v.y; As[c4*4+2][r]=v.z; As[c4*4+3][r]=v.w;
        }
#pragma unroll
        for (int i = tid; i < BN*BK/4; i += NT) {
            int r = i / (BK/4), c4 = i % (BK/4);
            float4 v = *reinterpret_cast<const float4*>(&B[(size_t)(n0+r)*K + k0 + c4*4]);
            Bs[c4*4+0][r]=v.x; Bs[c4*4+1][r]=v.y; Bs[c4*4+2][r]=v.z; Bs[c4*4+3][r]=v.w;
        }
        __syncthreads();
#pragma unroll
        for (int k = 0; k < BK; k++) {
            float ar[TM], br[TN];
#pragma unroll
            for (int i = 0; i < TM; i++) ar[i] = As[k][ty*TM+i];
#pragma unroll
            for (int j = 0; j < TN; j++) br[j] = Bs[k][tx*TN+j];
#pragma unroll
            for (int i = 0; i < TM; i++)
#pragma unroll
                for (int j = 0; j < TN; j++) acc[i][j] = fmaf(ar[i], br[j], acc[i][j]);
        }
        __syncthreads();
    }
#pragma unroll
    for (int i = 0; i < TM; i++) {
        float* crow = &C[(size_t)(m0+ty*TM+i)*N + n0 + tx*TN];
#pragma unroll
        for (int j = 0; j < TN; j++) crow[j] = acc[i][j];
    }
}

// ======================= pointwise / aux kernels =============================
__global__ void wcat_kernel(const float* __restrict__ Wx, const float* __restrict__ Wdt)
{
    int idx = blockIdx.x * blockDim.x + threadIdx.x;
    int row = idx >> 10;
    g_wcat[idx] = (row < DSTATE) ? Wdt[idx] : Wx[idx];
}

__global__ void conv_silu_kernel(const float* __restrict__ cw, const float* __restrict__ cb)
{
    int idx = blockIdx.x * blockDim.x + threadIdx.x;
    int c4 = idx & (DINNER/4 - 1);
    int m  = idx >> 8;
    int c  = c4 * 4;
    int l  = m & (SEQLEN - 1);
    float w[4][4];
#pragma unroll
    for (int j = 0; j < 4; j++)
        *reinterpret_cast<float4*>(w[j]) =
            *reinterpret_cast<const float4*>(cw + (size_t)(c + j) * DCONV);
    float4 b = *reinterpret_cast<const float4*>(cb + c);
    float a0 = b.x, a1 = b.y, a2 = b.z, a3 = b.w;
#pragma unroll
    for (int t = 0; t < DCONV; t++) {
        int ls = l - (DCONV - 1) + t;
        if (ls >= 0) {
            float4 xv = *reinterpret_cast<const float4*>(
                g_xr + (size_t)(m - (DCONV - 1) + t) * (2 * DINNER) + c);
            a0 = fmaf(w[0][t], xv.x, a0);
            a1 = fmaf(w[1][t], xv.y, a1);
            a2 = fmaf(w[2][t], xv.z, a2);
            a3 = fmaf(w[3][t], xv.w, a3);
        }
    }
    float4 o;
    o.x = a0 / (1.f + expf(-a0));
    o.y = a1 / (1.f + expf(-a1));
    o.z = a2 / (1.f + expf(-a2));
    o.w = a3 / (1.f + expf(-a3));
    *reinterpret_cast<float4*>(g_xa + (size_t)m * DINNER + c) = o;
}

__global__ void u_kernel()
{
    int gw = (blockIdx.x * blockDim.x + threadIdx.x) >> 5;
    int lane = threadIdx.x & 31;
    if (gw >= M_TOK) return;
    const float* xa = g_xa + (size_t)gw * DINNER;
    float v = xa[lane] + xa[lane + 32];
#pragma unroll
    for (int o = 16; o; o >>= 1) v += __shfl_down_sync(0xffffffffu, v, o);
    if (lane == 0) g_u[gw] = v * (1.f / 64.f);
}

__global__ void dtbu_kernel(const float* __restrict__ bdt, const float* __restrict__ Alog)
{
    int idx = blockIdx.x * blockDim.x + threadIdx.x;
    int m = idx >> 4;
    int n = idx & (DSTATE - 1);
    float raw = g_dtb[(size_t)m * 2 * DSTATE + n] + bdt[n];
    float dt  = raw > 20.f ? raw : log1pf(expf(raw));
    float bp  = g_dtb[(size_t)m * 2 * DSTATE + DSTATE + n];
    float A   = -expf(Alog[n]);
    g_adisc[idx] = expf(A * dt);
    g_bu[idx]    = dt * bp * g_u[m];
}

// -------- chunked scan (3 passes) --------
__global__ void scan_part_kernel()
{
    int t = blockIdx.x * blockDim.x + threadIdx.x;
    int chain = t >> 5, c = t & 31;
    int b = chain >> 4, n = chain & 15;
    size_t base = ((size_t)(b * SEQLEN + c * SCHUNK)) * DSTATE + n;
    float A = 1.f, V = 0.f;
#pragma unroll 8
    for (int i = 0; i < SCHUNK; i++) {
        float a = g_adisc[base + (size_t)i * DSTATE];
        float v = g_bu   [base + (size_t)i * DSTATE];
        V = fmaf(a, V, v);
        A *= a;
    }
    g_cA[chain * NCHUNK + c] = A;
    g_cV[chain * NCHUNK + c] = V;
}
__global__ void scan_mid_kernel()
{
    int chain = threadIdx.x;
    float s = 0.f;
#pragma unroll
    for (int c = 0; c < NCHUNK; c++) {
        g_carry[chain * NCHUNK + c] = s;
        s = fmaf(g_cA[chain * NCHUNK + c], s, g_cV[chain * NCHUNK + c]);
    }
}
__global__ void scan_apply_kernel()
{
    int t = blockIdx.x * blockDim.x + threadIdx.x;
    int chain = t >> 5, c = t & 31;
    int b = chain >> 4, n = chain & 15;
    size_t base = ((size_t)(b * SEQLEN + c * SCHUNK)) * DSTATE + n;
    float s = g_carry[chain * NCHUNK + c];
#pragma unroll 8
    for (int i = 0; i < SCHUNK; i++) {
        float a = g_adisc[base + (size_t)i * DSTATE];
        float v = g_bu   [base + (size_t)i * DSTATE];
        s = fmaf(a, s, v);
        g_y[base + (size_t)i * DSTATE] = s;
    }
}

// -------- gate + skip, fused bf16 [hi|lo] split output -----------------------
__global__ void elt_kernel(const float* __restrict__ Dp)
{
    int idx = blockIdx.x * blockDim.x + threadIdx.x;
    int c4 = idx & (DINNER/4 - 1);
    int m  = idx >> 8;
    int c  = c4 * 4;
    float yv  = g_y[(size_t)m * DSTATE + (c >> 6)];
    float4 xa = *reinterpret_cast<const float4*>(g_xa + (size_t)m * DINNER + c);
    float4 D  = *reinterpret_cast<const float4*>(Dp + c);
    float4 r  = *reinterpret_cast<const float4*>(g_xr + (size_t)m * 2 * DINNER + DINNER + c);
    float4 o;
    o.x = (yv + xa.x * D.x) * (r.x / (1.f + expf(-r.x)));
    o.y = (yv + xa.y * D.y) * (r.y / (1.f + expf(-r.y)));
    o.z = (yv + xa.z * D.z) * (r.z / (1.f + expf(-r.z)));
    o.w = (yv + xa.w * D.w) * (r.w / (1.f + expf(-r.w)));

    __nv_bfloat162 h01 = __floats2bfloat162_rn(o.x, o.y);
    __nv_bfloat162 h23 = __floats2bfloat162_rn(o.z, o.w);
    __nv_bfloat162 l01 = __floats2bfloat162_rn(o.x - __bfloat162float(h01.x),
                                               o.y - __bfloat162float(h01.y));
    __nv_bfloat162 l23 = __floats2bfloat162_rn(o.z - __bfloat162float(h23.x),
                                               o.w - __bfloat162float(h23.y));
    __nv_bfloat16* row = g_yb + (size_t)m * 2 * DINNER;
    *reinterpret_cast<__nv_bfloat162*>(row + c)              = h01;
    *reinterpret_cast<__nv_bfloat162*>(row + c + 2)          = h23;
    *reinterpret_cast<__nv_bfloat162*>(row + DINNER + c)     = l01;
    *reinterpret_cast<__nv_bfloat162*>(row + DINNER + c + 2) = l23;
}

// ======================= launch ==============================================
extern "C" void kernel_launch(void* const* d_in, const int* in_sizes, int n_in,
                              void* d_out, int out_size)
{
    const float* x      = (const float*)d_in[0];
    const float* W_in   = (const float*)d_in[1];
    const float* conv_w = (const float*)d_in[2];
    const float* conv_b = (const float*)d_in[3];
    const float* W_x    = (const float*)d_in[4];
    const float* W_dt   = (const float*)d_in[5];
    const float* b_dt   = (const float*)d_in[6];
    const float* A_log  = (const float*)d_in[7];
    const float* D_par  = (const float*)d_in[8];
    const float* W_out  = (const float*)d_in[9];
    float* out = (float*)d_out;

    float* xr;   cudaGetSymbolAddress((void**)&xr,   g_xr);
    float* xa;   cudaGetSymbolAddress((void**)&xa,   g_xa);
    float* wcat; cudaGetSymbolAddress((void**)&wcat, g_wcat);
    float* dtb;  cudaGetSymbolAddress((void**)&dtb,  g_dtb);
    __nv_bfloat16* xb;  cudaGetSymbolAddress((void**)&xb,  g_xb);
    __nv_bfloat16* wib; cudaGetSymbolAddress((void**)&wib, g_wib);
    __nv_bfloat16* yb;  cudaGetSymbolAddress((void**)&yb,  g_yb);
    __nv_bfloat16* wob; cudaGetSymbolAddress((void**)&wob, g_wob);

    cudaFuncSetAttribute(gemm_dual, cudaFuncAttributeMaxDynamicSharedMemorySize, GH_SMEM);

    // weight prep
    wcat_kernel<<<(2*DSTATE*DINNER)/256, 256>>>(W_x, W_dt);
    splitw_kernel<<<(2*DINNER*DIM)/256, 256>>>(W_in, wib, DIM);
    splitw_kernel<<<(DIM*DINNER)/256, 256>>>(W_out, wob, DINNER);
    splita_kernel<<<((long)M_TOK*DIM)/256, 256>>>(x, xb, DIM);

    // GEMM1: xr = x @ W_in^T   [16384 x 2048], Kv=1536, kmod=16, Astride=1024
    gemm_dual<<<dim3(2*DINNER/128, M_TOK/128), 256, GH_SMEM>>>(
        xb, wib, xr, 2*DINNER, 3*DIM, (2*DIM)/64, 2*DIM);

    conv_silu_kernel<<<(M_TOK*(DINNER/4))/256, 256>>>(conv_w, conv_b);
    u_kernel<<<(M_TOK*32)/256, 256>>>();

    // small GEMM: [16384 x 32 x 1024] fp32 SIMT
    gemm_nt<64,32,16,4,2><<<dim3(1, M_TOK/64), 256>>>(xa, wcat, dtb, M_TOK, 2*DSTATE, DINNER);

    dtbu_kernel<<<(M_TOK*DSTATE)/256, 256>>>(b_dt, A_log);

    scan_part_kernel<<<(BATCH*DSTATE*NCHUNK)/256, 256>>>();
    scan_mid_kernel<<<1, BATCH*DSTATE>>>();
    scan_apply_kernel<<<(BATCH*DSTATE*NCHUNK)/256, 256>>>();

    elt_kernel<<<(M_TOK*(DINNER/4))/256, 256>>>(D_par);

    // GEMM2: out = y_full @ W_out^T  [16384 x 512], Kv=3072, kmod=32, Astride=2048
    gemm_dual<<<dim3(DIM/128, M_TOK/128), 256, GH_SMEM>>>(
        yb, wob, out, DIM, 3*DINNER, (2*DINNER)/64, 2*DINNER);
}

// round 7
// speedup vs baseline: 5.0543x; 1.7296x over previous
#include <cuda_runtime.h>
#include <cuda_fp16.h>
#include <math.h>
#include <stdint.h>

#define BATCH   4
#define SEQLEN  4096
#define DIM     512
#define DINNER  1024
#define DSTATE  16
#define DCONV   4
#define M_TOK   (BATCH*SEQLEN)   // 16384

// ======================= PTX helpers (sm_80 baseline) ========================
__device__ __forceinline__ uint32_t smem_to_u32(const void* p) {
    uint32_t a;
    asm("{ .reg .u64 t; cvta.to.shared.u64 t, %1; cvt.u32.u64 %0, t; }"
        : "=r"(a) : "l"(p));
    return a;
}
#define CP_ASYNC16(saddr, gptr) \
    asm volatile("cp.async.cg.shared.global [%0], [%1], 16;" \
        :: "r"(saddr), "l"(gptr))
#define CP_COMMIT() asm volatile("cp.async.commit_group;" ::: "memory")
#define CP_WAIT1()  asm volatile("cp.async.wait_group 1;" ::: "memory")
#define CP_WAIT0()  asm volatile("cp.async.wait_group 0;" ::: "memory")

#define LDSM_X4(r, addr) \
    asm volatile("ldmatrix.sync.aligned.m8n8.x4.shared.b16 {%0,%1,%2,%3}, [%4];" \
        : "=r"((r)[0]), "=r"((r)[1]), "=r"((r)[2]), "=r"((r)[3]) : "r"(addr))

#define MMA_F16(d, a, b0, b1) \
    asm volatile("mma.sync.aligned.m16n8k16.row.col.f32.f16.f16.f32 " \
        "{%0,%1,%2,%3}, {%4,%5,%6,%7}, {%8,%9}, {%0,%1,%2,%3};" \
        : "+f"((d)[0]), "+f"((d)[1]), "+f"((d)[2]), "+f"((d)[3]) \
        : "r"((a)[0]), "r"((a)[1]), "r"((a)[2]), "r"((a)[3]), "r"(b0), "r"(b1))

// ======================= scratch =============================================
__device__ __align__(256) float g_xr  [(size_t)M_TOK * 2 * DINNER];
__device__ __align__(256) float g_xa  [(size_t)M_TOK * DINNER];
__device__ __align__(256) float g_wcat[2 * DSTATE * DINNER];
__device__ __align__(256) float g_dtb [(size_t)M_TOK * 2 * DSTATE];
__device__ __align__(256) float g_u   [M_TOK];
__device__ __align__(256) float g_adisc[(size_t)M_TOK * DSTATE];
__device__ __align__(256) float g_bu  [(size_t)M_TOK * DSTATE];
__device__ __align__(256) float g_y   [(size_t)M_TOK * DSTATE];
// fp16 GEMM operands (single precision plane, no split)
__device__ __align__(256) __half g_xh [(size_t)M_TOK * DIM];        // 16MB
__device__ __align__(256) __half g_yh [(size_t)M_TOK * DINNER];     // 32MB
__device__ __align__(256) __half g_wih[(size_t)2*DINNER * DIM];     // 2MB
__device__ __align__(256) __half g_woh[(size_t)DIM * DINNER];       // 1MB
// scan chunk summaries
#define SCHUNK  128
#define NCHUNK  (SEQLEN / SCHUNK)   // 32
__device__ float g_cA   [BATCH * DSTATE * NCHUNK];
__device__ float g_cV   [BATCH * DSTATE * NCHUNK];
__device__ float g_carry[BATCH * DSTATE * NCHUNK];

// ======================= HMMA fp16 GEMM ======================================
// C[M,N] = A[M,K] * B[N,K]^T, fp16 K-major inputs, fp32 out.
// Block tile 128x128, 256 threads (8 warps, 4x2, warp tile 32x64),
// K-chunk 64 halves (128B/row), cp.async double buffer, ldmatrix + mma.sync.
#define LG_ROWB   144
#define LG_TILE_B (128 * LG_ROWB)          // 18432 B
#define GH_SMEM   (4 * LG_TILE_B)          // 73728 B

__global__ __launch_bounds__(256, 2)
void gemm_hmma(const __half* __restrict__ A, const __half* __restrict__ B,
               float* __restrict__ C, int Nglob, int K)
{
    extern __shared__ char smem[];
    const uint32_t sb = smem_to_u32(smem);
    const int tid  = threadIdx.x;
    const int wid  = tid >> 5;
    const int lane = tid & 31;
    const int m0 = blockIdx.y * 128;
    const int n0 = blockIdx.x * 128;
    const int nch = K / 64;

    const int wm = (wid & 3) * 32;
    const int wn = (wid >> 2) * 64;
    const uint32_t offA[2] = { 0u,              2u * LG_TILE_B };
    const uint32_t offB[2] = { (uint32_t)LG_TILE_B, 3u * LG_TILE_B };

    float acc[2][8][4];
#pragma unroll
    for (int i = 0; i < 2; i++)
#pragma unroll
        for (int j = 0; j < 8; j++)
#pragma unroll
            for (int k = 0; k < 4; k++) acc[i][j][k] = 0.f;

    auto issue = [&](int c, int b) {
        const __half* Ag = A + (size_t)m0 * K + (size_t)c * 64;
        const __half* Bg = B + (size_t)n0 * K + (size_t)c * 64;
        const uint32_t sa  = sb + offA[b];
        const uint32_t sbm = sb + offB[b];
#pragma unroll
        for (int i = 0; i < 4; i++) {
            int idx = tid + i * 256;              // 0..1023
            int row = idx >> 3, cc = idx & 7;     // 8 x 16B per 128B row
            CP_ASYNC16(sa  + (uint32_t)(row * LG_ROWB + cc * 16),
                       Ag + (size_t)row * K + cc * 8);
            CP_ASYNC16(sbm + (uint32_t)(row * LG_ROWB + cc * 16),
                       Bg + (size_t)row * K + cc * 8);
        }
        CP_COMMIT();
    };

    issue(0, 0);
    for (int c = 0; c < nch; c++) {
        const int buf = c & 1;
        if (c + 1 < nch) { issue(c + 1, buf ^ 1); CP_WAIT1(); }
        else             { CP_WAIT0(); }
        __syncthreads();

        const uint32_t aBase = sb + offA[buf];
        const uint32_t bBase = sb + offB[buf];
        const int lrow = lane & 15;
        const int lcol = (lane >> 4) * 16;
#pragma unroll
        for (int ks = 0; ks < 4; ks++) {
            uint32_t af[2][4], bfr[4][4];
#pragma unroll
            for (int mt = 0; mt < 2; mt++)
                LDSM_X4(af[mt], aBase + (uint32_t)((wm + mt*16 + lrow) * LG_ROWB + ks*32 + lcol));
#pragma unroll
            for (int ng = 0; ng < 4; ng++)
                LDSM_X4(bfr[ng], bBase + (uint32_t)((wn + ng*16 + lrow) * LG_ROWB + ks*32 + lcol));
#pragma unroll
            for (int mt = 0; mt < 2; mt++)
#pragma unroll
                for (int nt = 0; nt < 8; nt++) {
                    const int ng = nt >> 1, hi = nt & 1;
                    MMA_F16(acc[mt][nt], af[mt], bfr[ng][hi], bfr[ng][2 + hi]);
                }
        }
        __syncthreads();
    }

    const int er = lane >> 2;
    const int ec = (lane & 3) * 2;
#pragma unroll
    for (int mt = 0; mt < 2; mt++) {
        const int rbase = m0 + wm + mt * 16;
#pragma unroll
        for (int nt = 0; nt < 8; nt++) {
            const int col = n0 + wn + nt * 8 + ec;
            *reinterpret_cast<float2*>(C + (size_t)(rbase + er)     * Nglob + col) =
                make_float2(acc[mt][nt][0], acc[mt][nt][1]);
            *reinterpret_cast<float2*>(C + (size_t)(rbase + er + 8) * Nglob + col) =
                make_float2(acc[mt][nt][2], acc[mt][nt][3]);
        }
    }
}

// ======================= fp32 -> fp16 conversion ==============================
__global__ void tohalf_kernel(const float* __restrict__ src, __half* __restrict__ dst)
{
    long i = ((long)blockIdx.x * blockDim.x + threadIdx.x) * 4;
    float4 v = *reinterpret_cast<const float4*>(src + i);
    __half2 h0 = __floats2half2_rn(v.x, v.y);
    __half2 h1 = __floats2half2_rn(v.z, v.w);
    *reinterpret_cast<__half2*>(dst + i)     = h0;
    *reinterpret_cast<__half2*>(dst + i + 2) = h1;
}

// ======================= SIMT NT GEMM (small dt/B_proj only) =================
template<int BM, int BN, int BK, int TM, int TN>
__global__ __launch_bounds__((BM/TM)*(BN/TN))
void gemm_nt(const float* __restrict__ A, const float* __restrict__ B,
             float* __restrict__ C, int M, int N, int K)
{
    constexpr int TX = BN / TN;
    constexpr int TY = BM / TM;
    constexpr int NT = TX * TY;
    __shared__ float As[BK][BM];
    __shared__ float Bs[BK][BN];
    const int tid = threadIdx.x;
    const int tx = tid % TX, ty = tid / TX;
    const int m0 = blockIdx.y * BM, n0 = blockIdx.x * BN;
    float acc[TM][TN];
#pragma unroll
    for (int i = 0; i < TM; i++)
#pragma unroll
        for (int j = 0; j < TN; j++) acc[i][j] = 0.f;
    for (int k0 = 0; k0 < K; k0 += BK) {
#pragma unroll
        for (int i = tid; i < BM*BK/4; i += NT) {
            int r = i / (BK/4), c4 = i % (BK/4);
            float4 v = *reinterpret_cast<const float4*>(&A[(size_t)(m0+r)*K + k0 + c4*4]);
            As[c4*4+0][r]=v.x; As[c4*4+1][r]=v.y; As[c4*4+2][r]=v.z; As[c4*4+3][r]=v.w;
        }
#pragma unroll
        for (int i = tid; i < BN*BK/4; i += NT) {
            int r = i / (BK/4), c4 = i % (BK/4);
            float4 v = *reinterpret_cast<const float4*>(&B[(size_t)(n0+r)*K + k0 + c4*4]);
            Bs[c4*4+0][r]=v.x; Bs[c4*4+1][r]=v.y; Bs[c4*4+2][r]=v.z; Bs[c4*4+3][r]=v.w;
        }
        __syncthreads();
#pragma unroll
        for (int k = 0; k < BK; k++) {
            float ar[TM], br[TN];
#pragma unroll
            for (int i = 0; i < TM; i++) ar[i] = As[k][ty*TM+i];
#pragma unroll
            for (int j = 0; j < TN; j++) br[j] = Bs[k][tx*TN+j];
#pragma unroll
            for (int i = 0; i < TM; i++)
#pragma unroll
                for (int j = 0; j < TN; j++) acc[i][j] = fmaf(ar[i], br[j], acc[i][j]);
        }
        __syncthreads();
    }
#pragma unroll
    for (int i = 0; i < TM; i++) {
        float* crow = &C[(size_t)(m0+ty*TM+i)*N + n0 + tx*TN];
#pragma unroll
        for (int j = 0; j < TN; j++) crow[j] = acc[i][j];
    }
}

// ======================= pointwise / aux kernels =============================
__global__ void wcat_kernel(const float* __restrict__ Wx, const float* __restrict__ Wdt)
{
    int idx = blockIdx.x * blockDim.x + threadIdx.x;
    int row = idx >> 10;
    g_wcat[idx] = (row < DSTATE) ? Wdt[idx] : Wx[idx];
}

__global__ void conv_silu_kernel(const float* __restrict__ cw, const float* __restrict__ cb)
{
    int idx = blockIdx.x * blockDim.x + threadIdx.x;
    int c4 = idx & (DINNER/4 - 1);
    int m  = idx >> 8;
    int c  = c4 * 4;
    int l  = m & (SEQLEN - 1);
    float w[4][4];
#pragma unroll
    for (int j = 0; j < 4; j++)
        *reinterpret_cast<float4*>(w[j]) =
            *reinterpret_cast<const float4*>(cw + (size_t)(c + j) * DCONV);
    float4 b = *reinterpret_cast<const float4*>(cb + c);
    float a0 = b.x, a1 = b.y, a2 = b.z, a3 = b.w;
#pragma unroll
    for (int t = 0; t < DCONV; t++) {
        int ls = l - (DCONV - 1) + t;
        if (ls >= 0) {
            float4 xv = *reinterpret_cast<const float4*>(
                g_xr + (size_t)(m - (DCONV - 1) + t) * (2 * DINNER) + c);
            a0 = fmaf(w[0][t], xv.x, a0);
            a1 = fmaf(w[1][t], xv.y, a1);
            a2 = fmaf(w[2][t], xv.z, a2);
            a3 = fmaf(w[3][t], xv.w, a3);
        }
    }
    float4 o;
    o.x = a0 / (1.f + expf(-a0));
    o.y = a1 / (1.f + expf(-a1));
    o.z = a2 / (1.f + expf(-a2));
    o.w = a3 / (1.f + expf(-a3));
    *reinterpret_cast<float4*>(g_xa + (size_t)m * DINNER + c) = o;
}

__global__ void u_kernel()
{
    int gw = (blockIdx.x * blockDim.x + threadIdx.x) >> 5;
    int lane = threadIdx.x & 31;
    if (gw >= M_TOK) return;
    const float* xa = g_xa + (size_t)gw * DINNER;
    float v = xa[lane] + xa[lane + 32];
#pragma unroll
    for (int o = 16; o; o >>= 1) v += __shfl_down_sync(0xffffffffu, v, o);
    if (lane == 0) g_u[gw] = v * (1.f / 64.f);
}

__global__ void dtbu_kernel(const float* __restrict__ bdt, const float* __restrict__ Alog)
{
    int idx = blockIdx.x * blockDim.x + threadIdx.x;
    int m = idx >> 4;
    int n = idx & (DSTATE - 1);
    float raw = g_dtb[(size_t)m * 2 * DSTATE + n] + bdt[n];
    float dt  = raw > 20.f ? raw : log1pf(expf(raw));
    float bp  = g_dtb[(size_t)m * 2 * DSTATE + DSTATE + n];
    float A   = -expf(Alog[n]);
    g_adisc[idx] = expf(A * dt);
    g_bu[idx]    = dt * bp * g_u[m];
}

// -------- chunked scan (3 passes) --------
__global__ void scan_part_kernel()
{
    int t = blockIdx.x * blockDim.x + threadIdx.x;
    int chain = t >> 5, c = t & 31;
    int b = chain >> 4, n = chain & 15;
    size_t base = ((size_t)(b * SEQLEN + c * SCHUNK)) * DSTATE + n;
    float A = 1.f, V = 0.f;
#pragma unroll 8
    for (int i = 0; i < SCHUNK; i++) {
        float a = g_adisc[base + (size_t)i * DSTATE];
        float v = g_bu   [base + (size_t)i * DSTATE];
        V = fmaf(a, V, v);
        A *= a;
    }
    g_cA[chain * NCHUNK + c] = A;
    g_cV[chain * NCHUNK + c] = V;
}
__global__ void scan_mid_kernel()
{
    int chain = threadIdx.x;
    float s = 0.f;
#pragma unroll
    for (int c = 0; c < NCHUNK; c++) {
        g_carry[chain * NCHUNK + c] = s;
        s = fmaf(g_cA[chain * NCHUNK + c], s, g_cV[chain * NCHUNK + c]);
    }
}
__global__ void scan_apply_kernel()
{
    int t = blockIdx.x * blockDim.x + threadIdx.x;
    int chain = t >> 5, c = t & 31;
    int b = chain >> 4, n = chain & 15;
    size_t base = ((size_t)(b * SEQLEN + c * SCHUNK)) * DSTATE + n;
    float s = g_carry[chain * NCHUNK + c];
#pragma unroll 8
    for (int i = 0; i < SCHUNK; i++) {
        float a = g_adisc[base + (size_t)i * DSTATE];
        float v = g_bu   [base + (size_t)i * DSTATE];
        s = fmaf(a, s, v);
        g_y[base + (size_t)i * DSTATE] = s;
    }
}

// -------- gate + skip, fp16 output for GEMM2 ---------------------------------
__global__ void elt_kernel(const float* __restrict__ Dp)
{
    int idx = blockIdx.x * blockDim.x + threadIdx.x;
    int c4 = idx & (DINNER/4 - 1);
    int m  = idx >> 8;
    int c  = c4 * 4;
    float yv  = g_y[(size_t)m * DSTATE + (c >> 6)];
    float4 xa = *reinterpret_cast<const float4*>(g_xa + (size_t)m * DINNER + c);
    float4 D  = *reinterpret_cast<const float4*>(Dp + c);
    float4 r  = *reinterpret_cast<const float4*>(g_xr + (size_t)m * 2 * DINNER + DINNER + c);
    float4 o;
    o.x = (yv + xa.x * D.x) * (r.x / (1.f + expf(-r.x)));
    o.y = (yv + xa.y * D.y) * (r.y / (1.f + expf(-r.y)));
    o.z = (yv + xa.z * D.z) * (r.z / (1.f + expf(-r.z)));
    o.w = (yv + xa.w * D.w) * (r.w / (1.f + expf(-r.w)));

    __half* row = g_yh + (size_t)m * DINNER;
    *reinterpret_cast<__half2*>(row + c)     = __floats2half2_rn(o.x, o.y);
    *reinterpret_cast<__half2*>(row + c + 2) = __floats2half2_rn(o.z, o.w);
}

// ======================= launch ==============================================
extern "C" void kernel_launch(void* const* d_in, const int* in_sizes, int n_in,
                              void* d_out, int out_size)
{
    const float* x      = (const float*)d_in[0];
    const float* W_in   = (const float*)d_in[1];
    const float* conv_w = (const float*)d_in[2];
    const float* conv_b = (const float*)d_in[3];
    const float* W_x    = (const float*)d_in[4];
    const float* W_dt   = (const float*)d_in[5];
    const float* b_dt   = (const float*)d_in[6];
    const float* A_log  = (const float*)d_in[7];
    const float* D_par  = (const float*)d_in[8];
    const float* W_out  = (const float*)d_in[9];
    float* out = (float*)d_out;

    float* xr;   cudaGetSymbolAddress((void**)&xr,   g_xr);
    float* xa;   cudaGetSymbolAddress((void**)&xa,   g_xa);
    float* wcat; cudaGetSymbolAddress((void**)&wcat, g_wcat);
    float* dtb;  cudaGetSymbolAddress((void**)&dtb,  g_dtb);
    __half* xh;  cudaGetSymbolAddress((void**)&xh,  g_xh);
    __half* yh;  cudaGetSymbolAddress((void**)&yh,  g_yh);
    __half* wih; cudaGetSymbolAddress((void**)&wih, g_wih);
    __half* woh; cudaGetSymbolAddress((void**)&woh, g_woh);

    cudaFuncSetAttribute(gemm_hmma, cudaFuncAttributeMaxDynamicSharedMemorySize, GH_SMEM);

    // weight / input conversion to fp16
    wcat_kernel<<<(2*DSTATE*DINNER)/256, 256>>>(W_x, W_dt);
    tohalf_kernel<<<(2*DINNER*DIM)/1024, 256>>>(W_in, wih);
    tohalf_kernel<<<(DIM*DINNER)/1024, 256>>>(W_out, woh);
    tohalf_kernel<<<((long)M_TOK*DIM)/1024, 256>>>(x, xh);

    // GEMM1: xr = x @ W_in^T   [16384 x 2048 x 512] fp16 HMMA
    gemm_hmma<<<dim3(2*DINNER/128, M_TOK/128), 256, GH_SMEM>>>(
        xh, wih, xr, 2*DINNER, DIM);

    conv_silu_kernel<<<(M_TOK*(DINNER/4))/256, 256>>>(conv_w, conv_b);
    u_kernel<<<(M_TOK*32)/256, 256>>>();

    // small GEMM: [16384 x 32 x 1024] fp32 SIMT (feeds exp-sensitive dt path)
    gemm_nt<64,32,16,4,2><<<dim3(1, M_TOK/64), 256>>>(xa, wcat, dtb, M_TOK, 2*DSTATE, DINNER);

    dtbu_kernel<<<(M_TOK*DSTATE)/256, 256>>>(b_dt, A_log);

    scan_part_kernel<<<(BATCH*DSTATE*NCHUNK)/256, 256>>>();
    scan_mid_kernel<<<1, BATCH*DSTATE>>>();
    scan_apply_kernel<<<(BATCH*DSTATE*NCHUNK)/256, 256>>>();

    elt_kernel<<<(M_TOK*(DINNER/4))/256, 256>>>(D_par);

    // GEMM2: out = y_full @ W_out^T  [16384 x 512 x 1024] fp16 HMMA
    gemm_hmma<<<dim3(DIM/128, M_TOK/128), 256, GH_SMEM>>>(
        yh, woh, out, DIM, DINNER);
}